// round 1
// baseline (speedup 1.0000x reference)
#include <cuda_runtime.h>
#include <math_constants.h>

// Problem shape (fixed for this dataset entry)
#define BB 2
#define LL 2048
#define HH 16
#define EE 64
#define DD 64
#define DMODEL 512
#define DHID 256

// scratch: fused MLP output per (b, l)
__device__ float g_fused[BB * LL];

// ---------------------------------------------------------------------------
// Kernel 1: fused MLP  fused[b,l] = (relu(raw @ w1 + b1) @ w2 + b2)
// One block = 16 positions, 256 threads (one hidden unit each).
// raw tile stored transposed (i-major) in smem so the inner loop reads it as
// broadcast float4 LDS; w1 column reads are fully coalesced LDG.
// ---------------------------------------------------------------------------
#define POS 16
#define RSTR 20   // padded stride: keeps 16B alignment (20*4=80B) and 2-way max bank conflict

__global__ __launch_bounds__(256) void mlp_kernel(
    const float* __restrict__ raw,
    const float* __restrict__ w1, const float* __restrict__ b1,
    const float* __restrict__ w2, const float* __restrict__ b2) {
  __shared__ float rawT[DMODEL * RSTR];
  __shared__ float red[POS][9];
  int tid = threadIdx.x;
  int p0 = blockIdx.x * POS;

  // load 16 x 512 raw tile, transposed to i-major
#pragma unroll
  for (int it = 0; it < 8; it++) {
    int f = tid + 256 * it;       // 2048 float4 total
    int p  = f >> 7;              // position 0..15
    int i4 = f & 127;             // float4 index along feature dim
    float4 x = *(const float4*)(raw + (size_t)(p0 + p) * DMODEL + i4 * 4);
    rawT[(i4 * 4 + 0) * RSTR + p] = x.x;
    rawT[(i4 * 4 + 1) * RSTR + p] = x.y;
    rawT[(i4 * 4 + 2) * RSTR + p] = x.z;
    rawT[(i4 * 4 + 3) * RSTR + p] = x.w;
  }
  __syncthreads();

  int j = tid;  // hidden unit
  float acc[POS];
#pragma unroll
  for (int p = 0; p < POS; p++) acc[p] = 0.f;

#pragma unroll 4
  for (int i = 0; i < DMODEL; i++) {
    float w = __ldg(w1 + (size_t)i * DHID + j);
    const float4* rp = (const float4*)(rawT + i * RSTR);
    float4 r0 = rp[0], r1 = rp[1], r2 = rp[2], r3 = rp[3];
    acc[0]  = fmaf(w, r0.x, acc[0]);  acc[1]  = fmaf(w, r0.y, acc[1]);
    acc[2]  = fmaf(w, r0.z, acc[2]);  acc[3]  = fmaf(w, r0.w, acc[3]);
    acc[4]  = fmaf(w, r1.x, acc[4]);  acc[5]  = fmaf(w, r1.y, acc[5]);
    acc[6]  = fmaf(w, r1.z, acc[6]);  acc[7]  = fmaf(w, r1.w, acc[7]);
    acc[8]  = fmaf(w, r2.x, acc[8]);  acc[9]  = fmaf(w, r2.y, acc[9]);
    acc[10] = fmaf(w, r2.z, acc[10]); acc[11] = fmaf(w, r2.w, acc[11]);
    acc[12] = fmaf(w, r3.x, acc[12]); acc[13] = fmaf(w, r3.y, acc[13]);
    acc[14] = fmaf(w, r3.z, acc[14]); acc[15] = fmaf(w, r3.w, acc[15]);
  }

  float bb1 = b1[j];
  float ww2 = w2[j];
  float c[POS];
#pragma unroll
  for (int p = 0; p < POS; p++) c[p] = fmaxf(acc[p] + bb1, 0.f) * ww2;

  // warp reduction over hidden units
#pragma unroll
  for (int m = 16; m > 0; m >>= 1) {
#pragma unroll
    for (int p = 0; p < POS; p++)
      c[p] += __shfl_xor_sync(0xffffffffu, c[p], m);
  }
  if ((tid & 31) == 0) {
#pragma unroll
    for (int p = 0; p < POS; p++) red[p][tid >> 5] = c[p];
  }
  __syncthreads();
  if (tid < POS) {
    float s = b2[0];
#pragma unroll
    for (int w = 0; w < 8; w++) s += red[tid][w];
    g_fused[p0 + tid] = s;
  }
}

// ---------------------------------------------------------------------------
// Kernel 2: causal flash attention with momentum bias.
// Block: 256 threads, BM=64 query rows x BN=64 keys, 4x4 register micro-tile.
// Q,K stored k-major (transposed) in smem -> conflict-free float4 LDS in the
// S-GEMM; P stored s-major -> same for the O-GEMM. Online softmax in fp32.
// logit = scale * (q.k - alpha_h * |m_q - m_k|), causal masked with -inf.
// ---------------------------------------------------------------------------
#define BM 64
#define BN 64
#define SSTR 68   // padded stride (68*4=272B, 16B-aligned rows)

#define SMEM_FLOATS (4 * EE * SSTR + BM + BN)
#define SMEM_BYTES (SMEM_FLOATS * 4)

__global__ __launch_bounds__(256) void attn_kernel(
    const float* __restrict__ qg, const float* __restrict__ kg,
    const float* __restrict__ vg, const float* __restrict__ at,
    float* __restrict__ out) {
  extern __shared__ float sm[];
  float* Qt = sm;                 // [EE][SSTR] k-major: Qt[k][r]
  float* Kt = Qt + EE * SSTR;     // [EE][SSTR] k-major: Kt[k][c]
  float* Vs = Kt + EE * SSTR;     // [BN][SSTR] natural: Vs[s][d]
  float* Pt = Vs + BN * SSTR;     // [BN][SSTR] s-major: Pt[s][r]
  float* mQ = Pt + BN * SSTR;     // [BM]
  float* mK = mQ + BM;            // [BN]

  int tid = threadIdx.x;
  int bh = blockIdx.y;
  int b = bh / HH, h = bh % HH;
  int row0 = blockIdx.x * BM;
  int tr = tid >> 4, tc = tid & 15;
  const float scale = 0.125f;  // 1/sqrt(64)
  float alphah = at[h];

  // ---- load Q tile (transposed) ----
  {
    int r = tid >> 2;
    int e0 = (tid & 3) * 16;
    const float* src = qg + ((size_t)((b * LL + row0 + r) * HH + h)) * EE + e0;
#pragma unroll
    for (int u = 0; u < 4; u++) {
      float4 x = *(const float4*)(src + 4 * u);
      Qt[(e0 + 4 * u + 0) * SSTR + r] = x.x;
      Qt[(e0 + 4 * u + 1) * SSTR + r] = x.y;
      Qt[(e0 + 4 * u + 2) * SSTR + r] = x.z;
      Qt[(e0 + 4 * u + 3) * SSTR + r] = x.w;
    }
  }
  if (tid < BM) {
    int l = row0 + tid;
    mQ[tid] = (l > 0) ? (g_fused[b * LL + l] - g_fused[b * LL + l - 1]) : 0.f;
  }

  float m_i[4], l_i[4], o[4][4];
#pragma unroll
  for (int i = 0; i < 4; i++) {
    m_i[i] = -CUDART_INF_F;
    l_i[i] = 0.f;
#pragma unroll
    for (int jj = 0; jj < 4; jj++) o[i][jj] = 0.f;
  }

  int ntiles = blockIdx.x + 1;  // causal: tiles 0..qtile
  for (int kt = 0; kt < ntiles; kt++) {
    int c0 = kt * BN;
    __syncthreads();  // prev iter's O-GEMM done; also covers initial Q/mQ writes

    // ---- load K (transposed) and V (natural) tiles ----
    {
      int r = tid >> 2;
      int e0 = (tid & 3) * 16;
      const float* ks = kg + ((size_t)((b * LL + c0 + r) * HH + h)) * EE + e0;
      const float* vs = vg + ((size_t)((b * LL + c0 + r) * HH + h)) * DD + e0;
#pragma unroll
      for (int u = 0; u < 4; u++) {
        float4 x = *(const float4*)(ks + 4 * u);
        Kt[(e0 + 4 * u + 0) * SSTR + r] = x.x;
        Kt[(e0 + 4 * u + 1) * SSTR + r] = x.y;
        Kt[(e0 + 4 * u + 2) * SSTR + r] = x.z;
        Kt[(e0 + 4 * u + 3) * SSTR + r] = x.w;
        float4 y = *(const float4*)(vs + 4 * u);
        *(float4*)(Vs + r * SSTR + e0 + 4 * u) = y;
      }
    }
    if (tid < BN) {
      int l = c0 + tid;
      mK[tid] = (l > 0) ? (g_fused[b * LL + l] - g_fused[b * LL + l - 1]) : 0.f;
    }
    __syncthreads();

    // ---- S = Q K^T (4x4 per thread) ----
    float acc[4][4];
#pragma unroll
    for (int i = 0; i < 4; i++)
#pragma unroll
      for (int jj = 0; jj < 4; jj++) acc[i][jj] = 0.f;

#pragma unroll 8
    for (int kk = 0; kk < EE; kk++) {
      float4 aq = *(const float4*)(Qt + kk * SSTR + 4 * tr);
      float4 bk = *(const float4*)(Kt + kk * SSTR + 4 * tc);
      acc[0][0] = fmaf(aq.x, bk.x, acc[0][0]);
      acc[0][1] = fmaf(aq.x, bk.y, acc[0][1]);
      acc[0][2] = fmaf(aq.x, bk.z, acc[0][2]);
      acc[0][3] = fmaf(aq.x, bk.w, acc[0][3]);
      acc[1][0] = fmaf(aq.y, bk.x, acc[1][0]);
      acc[1][1] = fmaf(aq.y, bk.y, acc[1][1]);
      acc[1][2] = fmaf(aq.y, bk.z, acc[1][2]);
      acc[1][3] = fmaf(aq.y, bk.w, acc[1][3]);
      acc[2][0] = fmaf(aq.z, bk.x, acc[2][0]);
      acc[2][1] = fmaf(aq.z, bk.y, acc[2][1]);
      acc[2][2] = fmaf(aq.z, bk.z, acc[2][2]);
      acc[2][3] = fmaf(aq.z, bk.w, acc[2][3]);
      acc[3][0] = fmaf(aq.w, bk.x, acc[3][0]);
      acc[3][1] = fmaf(aq.w, bk.y, acc[3][1]);
      acc[3][2] = fmaf(aq.w, bk.z, acc[3][2]);
      acc[3][3] = fmaf(aq.w, bk.w, acc[3][3]);
    }

    // ---- bias + causal mask + online softmax ----
    float mqv[4], mkv[4];
#pragma unroll
    for (int i = 0; i < 4; i++) mqv[i] = mQ[4 * tr + i];
#pragma unroll
    for (int jj = 0; jj < 4; jj++) mkv[jj] = mK[4 * tc + jj];

    int rbase = row0 + 4 * tr;
    int cbase = c0 + 4 * tc;
    float p[4][4], rmax[4];
#pragma unroll
    for (int i = 0; i < 4; i++) {
      float mm = -CUDART_INF_F;
#pragma unroll
      for (int jj = 0; jj < 4; jj++) {
        float x = (acc[i][jj] - alphah * fabsf(mqv[i] - mkv[jj])) * scale;
        x = (cbase + jj <= rbase + i) ? x : -CUDART_INF_F;
        p[i][jj] = x;
        mm = fmaxf(mm, x);
      }
      rmax[i] = mm;
    }
    // row-max reduce across the 16 threads of a row group (half-warp)
#pragma unroll
    for (int s = 1; s < 16; s <<= 1) {
#pragma unroll
      for (int i = 0; i < 4; i++)
        rmax[i] = fmaxf(rmax[i], __shfl_xor_sync(0xffffffffu, rmax[i], s));
    }

    float al[4], rsum[4];
#pragma unroll
    for (int i = 0; i < 4; i++) {
      float mnew = fmaxf(m_i[i], rmax[i]);
      al[i] = __expf(m_i[i] - mnew);
      m_i[i] = mnew;
      float s4 = 0.f;
#pragma unroll
      for (int jj = 0; jj < 4; jj++) {
        float e = __expf(p[i][jj] - mnew);
        p[i][jj] = e;
        s4 += e;
      }
      rsum[i] = s4;
    }
#pragma unroll
    for (int s = 1; s < 16; s <<= 1) {
#pragma unroll
      for (int i = 0; i < 4; i++)
        rsum[i] += __shfl_xor_sync(0xffffffffu, rsum[i], s);
    }
#pragma unroll
    for (int i = 0; i < 4; i++) {
      l_i[i] = l_i[i] * al[i] + rsum[i];
#pragma unroll
      for (int jj = 0; jj < 4; jj++) o[i][jj] *= al[i];
    }

    // ---- write P (s-major) ----
#pragma unroll
    for (int jj = 0; jj < 4; jj++) {
      float4 col = make_float4(p[0][jj], p[1][jj], p[2][jj], p[3][jj]);
      *(float4*)(Pt + (4 * tc + jj) * SSTR + 4 * tr) = col;
    }
    __syncthreads();

    // ---- O += P @ V ----
#pragma unroll 8
    for (int s = 0; s < BN; s++) {
      float4 ap = *(const float4*)(Pt + s * SSTR + 4 * tr);
      float4 bv = *(const float4*)(Vs + s * SSTR + 4 * tc);
      o[0][0] = fmaf(ap.x, bv.x, o[0][0]);
      o[0][1] = fmaf(ap.x, bv.y, o[0][1]);
      o[0][2] = fmaf(ap.x, bv.z, o[0][2]);
      o[0][3] = fmaf(ap.x, bv.w, o[0][3]);
      o[1][0] = fmaf(ap.y, bv.x, o[1][0]);
      o[1][1] = fmaf(ap.y, bv.y, o[1][1]);
      o[1][2] = fmaf(ap.y, bv.z, o[1][2]);
      o[1][3] = fmaf(ap.y, bv.w, o[1][3]);
      o[2][0] = fmaf(ap.z, bv.x, o[2][0]);
      o[2][1] = fmaf(ap.z, bv.y, o[2][1]);
      o[2][2] = fmaf(ap.z, bv.z, o[2][2]);
      o[2][3] = fmaf(ap.z, bv.w, o[2][3]);
      o[3][0] = fmaf(ap.w, bv.x, o[3][0]);
      o[3][1] = fmaf(ap.w, bv.y, o[3][1]);
      o[3][2] = fmaf(ap.w, bv.z, o[3][2]);
      o[3][3] = fmaf(ap.w, bv.w, o[3][3]);
    }
  }

  // ---- epilogue: normalize and store ----
#pragma unroll
  for (int i = 0; i < 4; i++) {
    float inv = 1.f / l_i[i];
    int rg = row0 + 4 * tr + i;
    float4 r = make_float4(o[i][0] * inv, o[i][1] * inv, o[i][2] * inv,
                           o[i][3] * inv);
    *(float4*)(out + ((size_t)((b * LL + rg) * HH + h)) * DD + 4 * tc) = r;
  }
}

// ---------------------------------------------------------------------------
extern "C" void kernel_launch(void* const* d_in, const int* in_sizes, int n_in,
                              void* d_out, int out_size) {
  const float* q   = (const float*)d_in[0];
  const float* k   = (const float*)d_in[1];
  const float* v   = (const float*)d_in[2];
  const float* raw = (const float*)d_in[3];
  const float* w1  = (const float*)d_in[4];
  const float* b1  = (const float*)d_in[5];
  const float* w2  = (const float*)d_in[6];
  const float* b2  = (const float*)d_in[7];
  const float* at  = (const float*)d_in[8];
  float* out = (float*)d_out;

  mlp_kernel<<<(BB * LL) / POS, 256>>>(raw, w1, b1, w2, b2);

  cudaFuncSetAttribute(attn_kernel, cudaFuncAttributeMaxDynamicSharedMemorySize,
                       SMEM_BYTES);
  dim3 grid(LL / BM, BB * HH);
  attn_kernel<<<grid, 256, SMEM_BYTES>>>(q, k, v, at, out);
}

// round 2
// speedup vs baseline: 1.0729x; 1.0729x over previous
#include <cuda_runtime.h>
#include <math_constants.h>

// Problem shape (fixed for this dataset entry)
#define BB 2
#define LL 2048
#define HH 16
#define EE 64
#define DD 64
#define DMODEL 512
#define DHID 256

// scratch: fused MLP output per (b, l)
__device__ float g_fused[BB * LL];

// ---------------------------------------------------------------------------
// Kernel 1: fused MLP  fused[b,l] = (relu(raw @ w1 + b1) @ w2 + b2)
// ---------------------------------------------------------------------------
#define POS 16
#define RSTR 20

__global__ __launch_bounds__(256) void mlp_kernel(
    const float* __restrict__ raw,
    const float* __restrict__ w1, const float* __restrict__ b1,
    const float* __restrict__ w2, const float* __restrict__ b2) {
  __shared__ float rawT[DMODEL * RSTR];
  __shared__ float red[POS][9];
  int tid = threadIdx.x;
  int p0 = blockIdx.x * POS;

#pragma unroll
  for (int it = 0; it < 8; it++) {
    int f = tid + 256 * it;
    int p  = f >> 7;
    int i4 = f & 127;
    float4 x = *(const float4*)(raw + (size_t)(p0 + p) * DMODEL + i4 * 4);
    rawT[(i4 * 4 + 0) * RSTR + p] = x.x;
    rawT[(i4 * 4 + 1) * RSTR + p] = x.y;
    rawT[(i4 * 4 + 2) * RSTR + p] = x.z;
    rawT[(i4 * 4 + 3) * RSTR + p] = x.w;
  }
  __syncthreads();

  int j = tid;
  float acc[POS];
#pragma unroll
  for (int p = 0; p < POS; p++) acc[p] = 0.f;

#pragma unroll 4
  for (int i = 0; i < DMODEL; i++) {
    float w = __ldg(w1 + (size_t)i * DHID + j);
    const float4* rp = (const float4*)(rawT + i * RSTR);
    float4 r0 = rp[0], r1 = rp[1], r2 = rp[2], r3 = rp[3];
    acc[0]  = fmaf(w, r0.x, acc[0]);  acc[1]  = fmaf(w, r0.y, acc[1]);
    acc[2]  = fmaf(w, r0.z, acc[2]);  acc[3]  = fmaf(w, r0.w, acc[3]);
    acc[4]  = fmaf(w, r1.x, acc[4]);  acc[5]  = fmaf(w, r1.y, acc[5]);
    acc[6]  = fmaf(w, r1.z, acc[6]);  acc[7]  = fmaf(w, r1.w, acc[7]);
    acc[8]  = fmaf(w, r2.x, acc[8]);  acc[9]  = fmaf(w, r2.y, acc[9]);
    acc[10] = fmaf(w, r2.z, acc[10]); acc[11] = fmaf(w, r2.w, acc[11]);
    acc[12] = fmaf(w, r3.x, acc[12]); acc[13] = fmaf(w, r3.y, acc[13]);
    acc[14] = fmaf(w, r3.z, acc[14]); acc[15] = fmaf(w, r3.w, acc[15]);
  }

  float bb1 = b1[j];
  float ww2 = w2[j];
  float c[POS];
#pragma unroll
  for (int p = 0; p < POS; p++) c[p] = fmaxf(acc[p] + bb1, 0.f) * ww2;

#pragma unroll
  for (int m = 16; m > 0; m >>= 1) {
#pragma unroll
    for (int p = 0; p < POS; p++)
      c[p] += __shfl_xor_sync(0xffffffffu, c[p], m);
  }
  if ((tid & 31) == 0) {
#pragma unroll
    for (int p = 0; p < POS; p++) red[p][tid >> 5] = c[p];
  }
  __syncthreads();
  if (tid < POS) {
    float s = b2[0];
#pragma unroll
    for (int w = 0; w < 8; w++) s += red[tid][w];
    g_fused[p0 + tid] = s;
  }
}

// ---------------------------------------------------------------------------
// Kernel 2: causal flash attention with momentum bias.
// Block: 256 threads, BM=128 query rows x BN=64 keys, 8x4 register micro-tile
// (thread grid 16x16). Q,K k-major in smem; P s-major. Heaviest q-tiles run
// first (reversed block index) for wave packing.
// ---------------------------------------------------------------------------
#define BM 128
#define BN 64
#define QSTR 132  // stride for [EE][BM] and [BN][BM] arrays (16B-aligned rows)
#define KSTR 68   // stride for [EE][BN] and [BN][DD] arrays

#define SMEM_FLOATS (EE * QSTR + EE * KSTR + BN * KSTR + BN * QSTR + BM + BN)
#define SMEM_BYTES (SMEM_FLOATS * 4)

__global__ __launch_bounds__(256, 2) void attn_kernel(
    const float* __restrict__ qg, const float* __restrict__ kg,
    const float* __restrict__ vg, const float* __restrict__ at,
    float* __restrict__ out) {
  extern __shared__ float sm[];
  float* Qt = sm;                 // [EE][QSTR] k-major: Qt[k][r]
  float* Kt = Qt + EE * QSTR;     // [EE][KSTR] k-major: Kt[k][c]
  float* Vs = Kt + EE * KSTR;     // [BN][KSTR] natural: Vs[s][d]
  float* Pt = Vs + BN * KSTR;     // [BN][QSTR] s-major: Pt[s][r]
  float* mQ = Pt + BN * QSTR;     // [BM]
  float* mK = mQ + BM;            // [BN]

  int tid = threadIdx.x;
  int bh = blockIdx.y;
  int b = bh / HH, h = bh % HH;
  int bx = gridDim.x - 1 - blockIdx.x;  // heaviest first
  int row0 = bx * BM;
  int tr = tid >> 4, tc = tid & 15;
  const float scale = 0.125f;  // 1/sqrt(64)
  float alphah = at[h];

  // ---- load Q tile (transposed, 128 rows x 64) ----
  {
    int r = tid >> 1;
    int e0 = (tid & 1) * 32;
    const float* src = qg + ((size_t)((b * LL + row0 + r) * HH + h)) * EE + e0;
#pragma unroll
    for (int u = 0; u < 8; u++) {
      float4 x = *(const float4*)(src + 4 * u);
      Qt[(e0 + 4 * u + 0) * QSTR + r] = x.x;
      Qt[(e0 + 4 * u + 1) * QSTR + r] = x.y;
      Qt[(e0 + 4 * u + 2) * QSTR + r] = x.z;
      Qt[(e0 + 4 * u + 3) * QSTR + r] = x.w;
    }
  }
  if (tid < BM) {
    int l = row0 + tid;
    mQ[tid] = (l > 0) ? (g_fused[b * LL + l] - g_fused[b * LL + l - 1]) : 0.f;
  }

  float m_i[8], l_i[8], o[8][4];
#pragma unroll
  for (int i = 0; i < 8; i++) {
    m_i[i] = -CUDART_INF_F;
    l_i[i] = 0.f;
#pragma unroll
    for (int jj = 0; jj < 4; jj++) o[i][jj] = 0.f;
  }

  int ntiles = 2 * (bx + 1);  // causal: key tiles 0 .. (row0+BM-1)/BN
  for (int kt = 0; kt < ntiles; kt++) {
    int c0 = kt * BN;
    __syncthreads();  // prev O-GEMM done reading Kt/Vs/Pt; covers Q/mQ writes

    // ---- load K (transposed) and V (natural) ----
    {
      int r = tid >> 2;
      int e0 = (tid & 3) * 16;
      const float* ks = kg + ((size_t)((b * LL + c0 + r) * HH + h)) * EE + e0;
      const float* vs = vg + ((size_t)((b * LL + c0 + r) * HH + h)) * DD + e0;
#pragma unroll
      for (int u = 0; u < 4; u++) {
        float4 x = *(const float4*)(ks + 4 * u);
        Kt[(e0 + 4 * u + 0) * KSTR + r] = x.x;
        Kt[(e0 + 4 * u + 1) * KSTR + r] = x.y;
        Kt[(e0 + 4 * u + 2) * KSTR + r] = x.z;
        Kt[(e0 + 4 * u + 3) * KSTR + r] = x.w;
        float4 y = *(const float4*)(vs + 4 * u);
        *(float4*)(Vs + r * KSTR + e0 + 4 * u) = y;
      }
    }
    if (tid < BN) {
      int l = c0 + tid;
      mK[tid] = (l > 0) ? (g_fused[b * LL + l] - g_fused[b * LL + l - 1]) : 0.f;
    }
    __syncthreads();

    // ---- S = Q K^T (8x4 per thread) ----
    float acc[8][4];
#pragma unroll
    for (int i = 0; i < 8; i++)
#pragma unroll
      for (int jj = 0; jj < 4; jj++) acc[i][jj] = 0.f;

#pragma unroll 4
    for (int kk = 0; kk < EE; kk++) {
      float4 a0 = *(const float4*)(Qt + kk * QSTR + 8 * tr);
      float4 a1 = *(const float4*)(Qt + kk * QSTR + 8 * tr + 4);
      float4 bk = *(const float4*)(Kt + kk * KSTR + 4 * tc);
      acc[0][0] = fmaf(a0.x, bk.x, acc[0][0]);
      acc[0][1] = fmaf(a0.x, bk.y, acc[0][1]);
      acc[0][2] = fmaf(a0.x, bk.z, acc[0][2]);
      acc[0][3] = fmaf(a0.x, bk.w, acc[0][3]);
      acc[1][0] = fmaf(a0.y, bk.x, acc[1][0]);
      acc[1][1] = fmaf(a0.y, bk.y, acc[1][1]);
      acc[1][2] = fmaf(a0.y, bk.z, acc[1][2]);
      acc[1][3] = fmaf(a0.y, bk.w, acc[1][3]);
      acc[2][0] = fmaf(a0.z, bk.x, acc[2][0]);
      acc[2][1] = fmaf(a0.z, bk.y, acc[2][1]);
      acc[2][2] = fmaf(a0.z, bk.z, acc[2][2]);
      acc[2][3] = fmaf(a0.z, bk.w, acc[2][3]);
      acc[3][0] = fmaf(a0.w, bk.x, acc[3][0]);
      acc[3][1] = fmaf(a0.w, bk.y, acc[3][1]);
      acc[3][2] = fmaf(a0.w, bk.z, acc[3][2]);
      acc[3][3] = fmaf(a0.w, bk.w, acc[3][3]);
      acc[4][0] = fmaf(a1.x, bk.x, acc[4][0]);
      acc[4][1] = fmaf(a1.x, bk.y, acc[4][1]);
      acc[4][2] = fmaf(a1.x, bk.z, acc[4][2]);
      acc[4][3] = fmaf(a1.x, bk.w, acc[4][3]);
      acc[5][0] = fmaf(a1.y, bk.x, acc[5][0]);
      acc[5][1] = fmaf(a1.y, bk.y, acc[5][1]);
      acc[5][2] = fmaf(a1.y, bk.z, acc[5][2]);
      acc[5][3] = fmaf(a1.y, bk.w, acc[5][3]);
      acc[6][0] = fmaf(a1.z, bk.x, acc[6][0]);
      acc[6][1] = fmaf(a1.z, bk.y, acc[6][1]);
      acc[6][2] = fmaf(a1.z, bk.z, acc[6][2]);
      acc[6][3] = fmaf(a1.z, bk.w, acc[6][3]);
      acc[7][0] = fmaf(a1.w, bk.x, acc[7][0]);
      acc[7][1] = fmaf(a1.w, bk.y, acc[7][1]);
      acc[7][2] = fmaf(a1.w, bk.z, acc[7][2]);
      acc[7][3] = fmaf(a1.w, bk.w, acc[7][3]);
    }

    // ---- bias + causal mask + online softmax ----
    float mqv[8], mkv[4];
#pragma unroll
    for (int i = 0; i < 8; i++) mqv[i] = mQ[8 * tr + i];
#pragma unroll
    for (int jj = 0; jj < 4; jj++) mkv[jj] = mK[4 * tc + jj];

    int rbase = row0 + 8 * tr;
    int cbase = c0 + 4 * tc;
    float rmax[8];
#pragma unroll
    for (int i = 0; i < 8; i++) {
      float mm = -CUDART_INF_F;
#pragma unroll
      for (int jj = 0; jj < 4; jj++) {
        float x = (acc[i][jj] - alphah * fabsf(mqv[i] - mkv[jj])) * scale;
        x = (cbase + jj <= rbase + i) ? x : -CUDART_INF_F;
        acc[i][jj] = x;
        mm = fmaxf(mm, x);
      }
      rmax[i] = mm;
    }
    // row reduction over the 16 threads sharing a row group
#pragma unroll
    for (int s = 1; s < 16; s <<= 1) {
#pragma unroll
      for (int i = 0; i < 8; i++)
        rmax[i] = fmaxf(rmax[i], __shfl_xor_sync(0xffffffffu, rmax[i], s));
    }

    float al[8], rsum[8];
#pragma unroll
    for (int i = 0; i < 8; i++) {
      float mnew = fmaxf(m_i[i], rmax[i]);
      al[i] = __expf(m_i[i] - mnew);
      m_i[i] = mnew;
      float s4 = 0.f;
#pragma unroll
      for (int jj = 0; jj < 4; jj++) {
        float e = __expf(acc[i][jj] - mnew);
        acc[i][jj] = e;
        s4 += e;
      }
      rsum[i] = s4;
    }
#pragma unroll
    for (int s = 1; s < 16; s <<= 1) {
#pragma unroll
      for (int i = 0; i < 8; i++)
        rsum[i] += __shfl_xor_sync(0xffffffffu, rsum[i], s);
    }
#pragma unroll
    for (int i = 0; i < 8; i++) {
      l_i[i] = l_i[i] * al[i] + rsum[i];
#pragma unroll
      for (int jj = 0; jj < 4; jj++) o[i][jj] *= al[i];
    }

    // ---- write P (s-major) ----
#pragma unroll
    for (int jj = 0; jj < 4; jj++) {
      float4 c0v = make_float4(acc[0][jj], acc[1][jj], acc[2][jj], acc[3][jj]);
      float4 c1v = make_float4(acc[4][jj], acc[5][jj], acc[6][jj], acc[7][jj]);
      float* base = Pt + (4 * tc + jj) * QSTR + 8 * tr;
      *(float4*)(base) = c0v;
      *(float4*)(base + 4) = c1v;
    }
    __syncthreads();

    // ---- O += P @ V ----
#pragma unroll 4
    for (int s = 0; s < BN; s++) {
      float4 a0 = *(const float4*)(Pt + s * QSTR + 8 * tr);
      float4 a1 = *(const float4*)(Pt + s * QSTR + 8 * tr + 4);
      float4 bv = *(const float4*)(Vs + s * KSTR + 4 * tc);
      o[0][0] = fmaf(a0.x, bv.x, o[0][0]);
      o[0][1] = fmaf(a0.x, bv.y, o[0][1]);
      o[0][2] = fmaf(a0.x, bv.z, o[0][2]);
      o[0][3] = fmaf(a0.x, bv.w, o[0][3]);
      o[1][0] = fmaf(a0.y, bv.x, o[1][0]);
      o[1][1] = fmaf(a0.y, bv.y, o[1][1]);
      o[1][2] = fmaf(a0.y, bv.z, o[1][2]);
      o[1][3] = fmaf(a0.y, bv.w, o[1][3]);
      o[2][0] = fmaf(a0.z, bv.x, o[2][0]);
      o[2][1] = fmaf(a0.z, bv.y, o[2][1]);
      o[2][2] = fmaf(a0.z, bv.z, o[2][2]);
      o[2][3] = fmaf(a0.z, bv.w, o[2][3]);
      o[3][0] = fmaf(a0.w, bv.x, o[3][0]);
      o[3][1] = fmaf(a0.w, bv.y, o[3][1]);
      o[3][2] = fmaf(a0.w, bv.z, o[3][2]);
      o[3][3] = fmaf(a0.w, bv.w, o[3][3]);
      o[4][0] = fmaf(a1.x, bv.x, o[4][0]);
      o[4][1] = fmaf(a1.x, bv.y, o[4][1]);
      o[4][2] = fmaf(a1.x, bv.z, o[4][2]);
      o[4][3] = fmaf(a1.x, bv.w, o[4][3]);
      o[5][0] = fmaf(a1.y, bv.x, o[5][0]);
      o[5][1] = fmaf(a1.y, bv.y, o[5][1]);
      o[5][2] = fmaf(a1.y, bv.z, o[5][2]);
      o[5][3] = fmaf(a1.y, bv.w, o[5][3]);
      o[6][0] = fmaf(a1.z, bv.x, o[6][0]);
      o[6][1] = fmaf(a1.z, bv.y, o[6][1]);
      o[6][2] = fmaf(a1.z, bv.z, o[6][2]);
      o[6][3] = fmaf(a1.z, bv.w, o[6][3]);
      o[7][0] = fmaf(a1.w, bv.x, o[7][0]);
      o[7][1] = fmaf(a1.w, bv.y, o[7][1]);
      o[7][2] = fmaf(a1.w, bv.z, o[7][2]);
      o[7][3] = fmaf(a1.w, bv.w, o[7][3]);
    }
  }

  // ---- epilogue: normalize and store ----
#pragma unroll
  for (int i = 0; i < 8; i++) {
    float inv = 1.f / l_i[i];
    int rg = row0 + 8 * tr + i;
    float4 r = make_float4(o[i][0] * inv, o[i][1] * inv, o[i][2] * inv,
                           o[i][3] * inv);
    *(float4*)(out + ((size_t)((b * LL + rg) * HH + h)) * DD + 4 * tc) = r;
  }
}

// ---------------------------------------------------------------------------
extern "C" void kernel_launch(void* const* d_in, const int* in_sizes, int n_in,
                              void* d_out, int out_size) {
  const float* q   = (const float*)d_in[0];
  const float* k   = (const float*)d_in[1];
  const float* v   = (const float*)d_in[2];
  const float* raw = (const float*)d_in[3];
  const float* w1  = (const float*)d_in[4];
  const float* b1  = (const float*)d_in[5];
  const float* w2  = (const float*)d_in[6];
  const float* b2  = (const float*)d_in[7];
  const float* at  = (const float*)d_in[8];
  float* out = (float*)d_out;

  mlp_kernel<<<(BB * LL) / POS, 256>>>(raw, w1, b1, w2, b2);

  cudaFuncSetAttribute(attn_kernel, cudaFuncAttributeMaxDynamicSharedMemorySize,
                       SMEM_BYTES);
  dim3 grid(LL / BM, BB * HH);
  attn_kernel<<<grid, 256, SMEM_BYTES>>>(q, k, v, at, out);
}

// round 4
// speedup vs baseline: 1.9376x; 1.8058x over previous
#include <cuda_runtime.h>
#include <cuda_fp16.h>
#include <math_constants.h>
#include <cstdint>

// Problem shape (fixed)
#define BB 2
#define LL 2048
#define HH 16
#define EE 64
#define DD 64
#define DMODEL 512
#define DHID 256

__device__ float g_fused[BB * LL];

// ============================================================================
// Kernel 1: fused MLP (unchanged — not the bottleneck)
// ============================================================================
#define POS 16
#define RSTR 20

__global__ __launch_bounds__(256) void mlp_kernel(
    const float* __restrict__ raw,
    const float* __restrict__ w1, const float* __restrict__ b1,
    const float* __restrict__ w2, const float* __restrict__ b2) {
  __shared__ float rawT[DMODEL * RSTR];
  __shared__ float red[POS][9];
  int tid = threadIdx.x;
  int p0 = blockIdx.x * POS;

#pragma unroll
  for (int it = 0; it < 8; it++) {
    int f = tid + 256 * it;
    int p = f >> 7;
    int i4 = f & 127;
    float4 x = *(const float4*)(raw + (size_t)(p0 + p) * DMODEL + i4 * 4);
    rawT[(i4 * 4 + 0) * RSTR + p] = x.x;
    rawT[(i4 * 4 + 1) * RSTR + p] = x.y;
    rawT[(i4 * 4 + 2) * RSTR + p] = x.z;
    rawT[(i4 * 4 + 3) * RSTR + p] = x.w;
  }
  __syncthreads();

  int j = tid;
  float acc[POS];
#pragma unroll
  for (int p = 0; p < POS; p++) acc[p] = 0.f;

#pragma unroll 4
  for (int i = 0; i < DMODEL; i++) {
    float w = __ldg(w1 + (size_t)i * DHID + j);
    const float4* rp = (const float4*)(rawT + i * RSTR);
    float4 r0 = rp[0], r1 = rp[1], r2 = rp[2], r3 = rp[3];
    acc[0] = fmaf(w, r0.x, acc[0]);   acc[1] = fmaf(w, r0.y, acc[1]);
    acc[2] = fmaf(w, r0.z, acc[2]);   acc[3] = fmaf(w, r0.w, acc[3]);
    acc[4] = fmaf(w, r1.x, acc[4]);   acc[5] = fmaf(w, r1.y, acc[5]);
    acc[6] = fmaf(w, r1.z, acc[6]);   acc[7] = fmaf(w, r1.w, acc[7]);
    acc[8] = fmaf(w, r2.x, acc[8]);   acc[9] = fmaf(w, r2.y, acc[9]);
    acc[10] = fmaf(w, r2.z, acc[10]); acc[11] = fmaf(w, r2.w, acc[11]);
    acc[12] = fmaf(w, r3.x, acc[12]); acc[13] = fmaf(w, r3.y, acc[13]);
    acc[14] = fmaf(w, r3.z, acc[14]); acc[15] = fmaf(w, r3.w, acc[15]);
  }

  float bb1 = b1[j];
  float ww2 = w2[j];
  float c[POS];
#pragma unroll
  for (int p = 0; p < POS; p++) c[p] = fmaxf(acc[p] + bb1, 0.f) * ww2;
#pragma unroll
  for (int m = 16; m > 0; m >>= 1) {
#pragma unroll
    for (int p = 0; p < POS; p++)
      c[p] += __shfl_xor_sync(0xffffffffu, c[p], m);
  }
  if ((tid & 31) == 0) {
#pragma unroll
    for (int p = 0; p < POS; p++) red[p][tid >> 5] = c[p];
  }
  __syncthreads();
  if (tid < POS) {
    float s = b2[0];
#pragma unroll
    for (int w = 0; w < 8; w++) s += red[tid][w];
    g_fused[p0 + tid] = s;
  }
}

// ============================================================================
// Kernel 2: flash attention on mma.sync (m16n8k16 fp16->fp32), 2-term fp16
// split (3 MMAs per GEMM). 4 warps, BM=64 (16 rows/warp), BN=64.
// ============================================================================
#define Bb 64
#define BNk 64
#define HSTR 36  // half2 row stride (32 data + 4 pad) -> conflict-free frags

// smem offsets in 32-bit (half2) units
#define O_QHI 0
#define O_QLO (O_QHI + 64 * HSTR)
#define O_KHI (O_QLO + 64 * HSTR)
#define O_KLO (O_KHI + 64 * HSTR)
#define O_VHI (O_KLO + 64 * HSTR)
#define O_VLO (O_VHI + 64 * HSTR)
#define O_MK  (O_VLO + 64 * HSTR)
#define ATT_SMEM ((O_MK + 64) * 4)

#define MMA16816(d, a, b)                                                   \
  asm volatile(                                                             \
      "mma.sync.aligned.m16n8k16.row.col.f32.f16.f16.f32 "                  \
      "{%0,%1,%2,%3}, {%4,%5,%6,%7}, {%8,%9}, {%0,%1,%2,%3};"               \
      : "+f"((d)[0]), "+f"((d)[1]), "+f"((d)[2]), "+f"((d)[3])              \
      : "r"((a)[0]), "r"((a)[1]), "r"((a)[2]), "r"((a)[3]), "r"((b)[0]),    \
        "r"((b)[1]))

__device__ __forceinline__ void splitH2(float x0, float x1, uint32_t& hi,
                                        uint32_t& lo) {
  __half2 h = __floats2half2_rn(x0, x1);
  float2 hf = __half22float2(h);
  __half2 l = __floats2half2_rn(x0 - hf.x, x1 - hf.y);
  hi = *(uint32_t*)&h;
  lo = *(uint32_t*)&l;
}
__device__ __forceinline__ float ex2f(float x) {
  float r;
  asm("ex2.approx.ftz.f32 %0, %1;" : "=f"(r) : "f"(x));
  return r;
}

__global__ void __launch_bounds__(128) attn_kernel(
    const float* __restrict__ qg, const float* __restrict__ kg,
    const float* __restrict__ vg, const float* __restrict__ at,
    float* __restrict__ out) {
  extern __shared__ uint32_t sm[];
  float* mk = (float*)(sm + O_MK);

  int tid = threadIdx.x;
  int w = tid >> 5, lane = tid & 31;
  int quad = lane >> 2, four = lane & 3;
  int bh = blockIdx.y;
  int b = bh >> 4, h = bh & 15;
  int bx = (int)gridDim.x - 1 - (int)blockIdx.x;  // heaviest first
  int row0 = bx * Bb;

  const float sc = 0.125f * 1.44269504f;  // scale * log2(e)
  float alphaeff = at[h] * sc;

  // ---- load Q (scaled), split fp16 hi/lo ----
  {
    int r = tid >> 1;
    int e0 = (tid & 1) * 32;
    const float* src = qg + ((size_t)((b * LL + row0 + r) * HH + h)) * EE + e0;
    uint32_t* qh = sm + O_QHI + r * HSTR + (e0 >> 1);
    uint32_t* ql = sm + O_QLO + r * HSTR + (e0 >> 1);
#pragma unroll
    for (int u = 0; u < 8; u++) {
      float4 x = *(const float4*)(src + 4 * u);
      uint32_t h01, l01, h23, l23;
      splitH2(x.x * sc, x.y * sc, h01, l01);
      splitH2(x.z * sc, x.w * sc, h23, l23);
      qh[2 * u] = h01; qh[2 * u + 1] = h23;
      ql[2 * u] = l01; ql[2 * u + 1] = l23;
    }
  }

  // momentum for my two rows
  int r0g = row0 + 16 * w + quad;
  int r1g = r0g + 8;
  float mq0 = (r0g > 0) ? (g_fused[b * LL + r0g] - g_fused[b * LL + r0g - 1]) : 0.f;
  float mq1 = (g_fused[b * LL + r1g] - g_fused[b * LL + r1g - 1]);

  float oA[8][4];
#pragma unroll
  for (int nt = 0; nt < 8; nt++)
#pragma unroll
    for (int c = 0; c < 4; c++) oA[nt][c] = 0.f;
  float m0 = -CUDART_INF_F, m1 = -CUDART_INF_F, l0 = 0.f, l1 = 0.f;

  int ntiles = bx + 1;
  for (int kt = 0; kt < ntiles; kt++) {
    int c0 = kt * BNk;
    __syncthreads();  // safe to overwrite K/V (covers Q write on kt=0)

    // ---- load K hi/lo ----
    {
      int r = tid >> 1;
      int e0 = (tid & 1) * 32;
      const float* src = kg + ((size_t)((b * LL + c0 + r) * HH + h)) * EE + e0;
      uint32_t* kh = sm + O_KHI + r * HSTR + (e0 >> 1);
      uint32_t* kl = sm + O_KLO + r * HSTR + (e0 >> 1);
#pragma unroll
      for (int u = 0; u < 8; u++) {
        float4 x = *(const float4*)(src + 4 * u);
        uint32_t h01, l01, h23, l23;
        splitH2(x.x, x.y, h01, l01);
        splitH2(x.z, x.w, h23, l23);
        kh[2 * u] = h01; kh[2 * u + 1] = h23;
        kl[2 * u] = l01; kl[2 * u + 1] = l23;
      }
    }
    // ---- load V transposed: Vt[d][s/2] hi/lo ----
    {
      int sp = tid & 31;        // s pair
      int d0 = (tid >> 5) * 16; // 16 d per warp-group
      const float* va = vg + ((size_t)((b * LL + c0 + 2 * sp) * HH + h)) * DD + d0;
      const float* vb = va + (size_t)HH * DD;
#pragma unroll
      for (int u = 0; u < 4; u++) {
        float4 xa = *(const float4*)(va + 4 * u);
        float4 xb = *(const float4*)(vb + 4 * u);
        uint32_t hi, lo;
        splitH2(xa.x, xb.x, hi, lo);
        sm[O_VHI + (d0 + 4 * u + 0) * HSTR + sp] = hi;
        sm[O_VLO + (d0 + 4 * u + 0) * HSTR + sp] = lo;
        splitH2(xa.y, xb.y, hi, lo);
        sm[O_VHI + (d0 + 4 * u + 1) * HSTR + sp] = hi;
        sm[O_VLO + (d0 + 4 * u + 1) * HSTR + sp] = lo;
        splitH2(xa.z, xb.z, hi, lo);
        sm[O_VHI + (d0 + 4 * u + 2) * HSTR + sp] = hi;
        sm[O_VLO + (d0 + 4 * u + 2) * HSTR + sp] = lo;
        splitH2(xa.w, xb.w, hi, lo);
        sm[O_VHI + (d0 + 4 * u + 3) * HSTR + sp] = hi;
        sm[O_VLO + (d0 + 4 * u + 3) * HSTR + sp] = lo;
      }
    }
    if (tid < BNk) {
      int l = c0 + tid;
      mk[tid] = (l > 0) ? (g_fused[b * LL + l] - g_fused[b * LL + l - 1]) : 0.f;
    }
    __syncthreads();

    // ---- A fragments of Q (hi/lo), 4 k-tiles ----
    uint32_t aqh[4][4], aql[4][4];
    {
      int r = 16 * w + quad;
#pragma unroll
      for (int kk = 0; kk < 4; kk++) {
        int cA = kk * 8 + four;
        aqh[kk][0] = sm[O_QHI + r * HSTR + cA];
        aqh[kk][1] = sm[O_QHI + (r + 8) * HSTR + cA];
        aqh[kk][2] = sm[O_QHI + r * HSTR + cA + 4];
        aqh[kk][3] = sm[O_QHI + (r + 8) * HSTR + cA + 4];
        aql[kk][0] = sm[O_QLO + r * HSTR + cA];
        aql[kk][1] = sm[O_QLO + (r + 8) * HSTR + cA];
        aql[kk][2] = sm[O_QLO + r * HSTR + cA + 4];
        aql[kk][3] = sm[O_QLO + (r + 8) * HSTR + cA + 4];
      }
    }

    // ---- S = Q K^T ----
    float sA[8][4];
#pragma unroll
    for (int nt = 0; nt < 8; nt++)
#pragma unroll
      for (int c = 0; c < 4; c++) sA[nt][c] = 0.f;

#pragma unroll
    for (int nt = 0; nt < 8; nt++) {
      int srow = nt * 8 + quad;
#pragma unroll
      for (int kk = 0; kk < 4; kk++) {
        int cB = kk * 8 + four;
        uint32_t bhv[2], blv[2];
        bhv[0] = sm[O_KHI + srow * HSTR + cB];
        bhv[1] = sm[O_KHI + srow * HSTR + cB + 4];
        blv[0] = sm[O_KLO + srow * HSTR + cB];
        blv[1] = sm[O_KLO + srow * HSTR + cB + 4];
        MMA16816(sA[nt], aqh[kk], bhv);
        MMA16816(sA[nt], aqh[kk], blv);
        MMA16816(sA[nt], aql[kk], bhv);
      }
    }

    // ---- bias + causal mask + online softmax (base-2) ----
    float mx0 = -CUDART_INF_F, mx1 = -CUDART_INF_F;
    bool diag = (kt == bx);
#pragma unroll
    for (int nt = 0; nt < 8; nt++) {
      int cA = nt * 8 + four * 2;
      float mkA = mk[cA], mkB = mk[cA + 1];
      float x0 = sA[nt][0] - alphaeff * fabsf(mq0 - mkA);
      float x1 = sA[nt][1] - alphaeff * fabsf(mq0 - mkB);
      float x2 = sA[nt][2] - alphaeff * fabsf(mq1 - mkA);
      float x3 = sA[nt][3] - alphaeff * fabsf(mq1 - mkB);
      if (diag) {
        int cg = c0 + cA;
        x0 = (cg <= r0g) ? x0 : -CUDART_INF_F;
        x1 = (cg + 1 <= r0g) ? x1 : -CUDART_INF_F;
        x2 = (cg <= r1g) ? x2 : -CUDART_INF_F;
        x3 = (cg + 1 <= r1g) ? x3 : -CUDART_INF_F;
      }
      sA[nt][0] = x0; sA[nt][1] = x1; sA[nt][2] = x2; sA[nt][3] = x3;
      mx0 = fmaxf(mx0, fmaxf(x0, x1));
      mx1 = fmaxf(mx1, fmaxf(x2, x3));
    }
    mx0 = fmaxf(mx0, __shfl_xor_sync(0xffffffffu, mx0, 1));
    mx0 = fmaxf(mx0, __shfl_xor_sync(0xffffffffu, mx0, 2));
    mx1 = fmaxf(mx1, __shfl_xor_sync(0xffffffffu, mx1, 1));
    mx1 = fmaxf(mx1, __shfl_xor_sync(0xffffffffu, mx1, 2));

    float mn0 = fmaxf(m0, mx0), mn1 = fmaxf(m1, mx1);
    float al0 = ex2f(m0 - mn0), al1 = ex2f(m1 - mn1);
    m0 = mn0; m1 = mn1;

    float rs0 = 0.f, rs1 = 0.f;
#pragma unroll
    for (int nt = 0; nt < 8; nt++) {
      float e0v = ex2f(sA[nt][0] - mn0);
      float e1v = ex2f(sA[nt][1] - mn0);
      float e2v = ex2f(sA[nt][2] - mn1);
      float e3v = ex2f(sA[nt][3] - mn1);
      sA[nt][0] = e0v; sA[nt][1] = e1v; sA[nt][2] = e2v; sA[nt][3] = e3v;
      rs0 += e0v + e1v;
      rs1 += e2v + e3v;
    }
    rs0 += __shfl_xor_sync(0xffffffffu, rs0, 1);
    rs0 += __shfl_xor_sync(0xffffffffu, rs0, 2);
    rs1 += __shfl_xor_sync(0xffffffffu, rs1, 1);
    rs1 += __shfl_xor_sync(0xffffffffu, rs1, 2);
    l0 = l0 * al0 + rs0;
    l1 = l1 * al1 + rs1;

    // rescale O
#pragma unroll
    for (int nt = 0; nt < 8; nt++) {
      oA[nt][0] *= al0; oA[nt][1] *= al0;
      oA[nt][2] *= al1; oA[nt][3] *= al1;
    }

    // ---- pack P fragments (A of PV) in registers ----
    uint32_t ph[4][4], pl[4][4];
#pragma unroll
    for (int t = 0; t < 4; t++) {
      splitH2(sA[2 * t][0], sA[2 * t][1], ph[t][0], pl[t][0]);
      splitH2(sA[2 * t][2], sA[2 * t][3], ph[t][1], pl[t][1]);
      splitH2(sA[2 * t + 1][0], sA[2 * t + 1][1], ph[t][2], pl[t][2]);
      splitH2(sA[2 * t + 1][2], sA[2 * t + 1][3], ph[t][3], pl[t][3]);
    }

    // ---- O += P V ----
#pragma unroll
    for (int nt = 0; nt < 8; nt++) {
      int drow = nt * 8 + quad;
#pragma unroll
      for (int t = 0; t < 4; t++) {
        int cB = t * 8 + four;
        uint32_t bhv[2], blv[2];
        bhv[0] = sm[O_VHI + drow * HSTR + cB];
        bhv[1] = sm[O_VHI + drow * HSTR + cB + 4];
        blv[0] = sm[O_VLO + drow * HSTR + cB];
        blv[1] = sm[O_VLO + drow * HSTR + cB + 4];
        MMA16816(oA[nt], ph[t], bhv);
        MMA16816(oA[nt], ph[t], blv);
        MMA16816(oA[nt], pl[t], bhv);
      }
    }
  }

  // ---- epilogue ----
  float inv0 = 1.f / l0, inv1 = 1.f / l1;
  float* d0p = out + ((size_t)((b * LL + r0g) * HH + h)) * DD;
  float* d1p = out + ((size_t)((b * LL + r1g) * HH + h)) * DD;
#pragma unroll
  for (int nt = 0; nt < 8; nt++) {
    int c = nt * 8 + four * 2;
    *(float2*)(d0p + c) = make_float2(oA[nt][0] * inv0, oA[nt][1] * inv0);
    *(float2*)(d1p + c) = make_float2(oA[nt][2] * inv1, oA[nt][3] * inv1);
  }
}

// ---------------------------------------------------------------------------
extern "C" void kernel_launch(void* const* d_in, const int* in_sizes, int n_in,
                              void* d_out, int out_size) {
  const float* q = (const float*)d_in[0];
  const float* k = (const float*)d_in[1];
  const float* v = (const float*)d_in[2];
  const float* raw = (const float*)d_in[3];
  const float* w1 = (const float*)d_in[4];
  const float* b1 = (const float*)d_in[5];
  const float* w2 = (const float*)d_in[6];
  const float* b2 = (const float*)d_in[7];
  const float* at = (const float*)d_in[8];
  float* out = (float*)d_out;

  mlp_kernel<<<(BB * LL) / POS, 256>>>(raw, w1, b1, w2, b2);

  cudaFuncSetAttribute(attn_kernel, cudaFuncAttributeMaxDynamicSharedMemorySize,
                       ATT_SMEM);
  dim3 grid(LL / Bb, BB * HH);
  attn_kernel<<<grid, 128, ATT_SMEM>>>(q, k, v, at, out);
}

// round 6
// speedup vs baseline: 1.9665x; 1.0149x over previous
#include <cuda_runtime.h>
#include <cuda_fp16.h>
#include <math_constants.h>
#include <cstdint>

// Problem shape (fixed)
#define BB 2
#define LL 2048
#define HH 16
#define EE 64
#define DD 64
#define DMODEL 512
#define DHID 256

__device__ float g_fused[BB * LL];

// ============================================================================
// Kernel 1: fused MLP (unchanged — not the bottleneck)
// ============================================================================
#define POS 16
#define RSTR 20

__global__ __launch_bounds__(256) void mlp_kernel(
    const float* __restrict__ raw,
    const float* __restrict__ w1, const float* __restrict__ b1,
    const float* __restrict__ w2, const float* __restrict__ b2) {
  __shared__ float rawT[DMODEL * RSTR];
  __shared__ float red[POS][9];
  int tid = threadIdx.x;
  int p0 = blockIdx.x * POS;

#pragma unroll
  for (int it = 0; it < 8; it++) {
    int f = tid + 256 * it;
    int p = f >> 7;
    int i4 = f & 127;
    float4 x = *(const float4*)(raw + (size_t)(p0 + p) * DMODEL + i4 * 4);
    rawT[(i4 * 4 + 0) * RSTR + p] = x.x;
    rawT[(i4 * 4 + 1) * RSTR + p] = x.y;
    rawT[(i4 * 4 + 2) * RSTR + p] = x.z;
    rawT[(i4 * 4 + 3) * RSTR + p] = x.w;
  }
  __syncthreads();

  int j = tid;
  float acc[POS];
#pragma unroll
  for (int p = 0; p < POS; p++) acc[p] = 0.f;

#pragma unroll 4
  for (int i = 0; i < DMODEL; i++) {
    float w = __ldg(w1 + (size_t)i * DHID + j);
    const float4* rp = (const float4*)(rawT + i * RSTR);
    float4 r0 = rp[0], r1 = rp[1], r2 = rp[2], r3 = rp[3];
    acc[0] = fmaf(w, r0.x, acc[0]);   acc[1] = fmaf(w, r0.y, acc[1]);
    acc[2] = fmaf(w, r0.z, acc[2]);   acc[3] = fmaf(w, r0.w, acc[3]);
    acc[4] = fmaf(w, r1.x, acc[4]);   acc[5] = fmaf(w, r1.y, acc[5]);
    acc[6] = fmaf(w, r1.z, acc[6]);   acc[7] = fmaf(w, r1.w, acc[7]);
    acc[8] = fmaf(w, r2.x, acc[8]);   acc[9] = fmaf(w, r2.y, acc[9]);
    acc[10] = fmaf(w, r2.z, acc[10]); acc[11] = fmaf(w, r2.w, acc[11]);
    acc[12] = fmaf(w, r3.x, acc[12]); acc[13] = fmaf(w, r3.y, acc[13]);
    acc[14] = fmaf(w, r3.z, acc[14]); acc[15] = fmaf(w, r3.w, acc[15]);
  }

  float bb1 = b1[j];
  float ww2 = w2[j];
  float c[POS];
#pragma unroll
  for (int p = 0; p < POS; p++) c[p] = fmaxf(acc[p] + bb1, 0.f) * ww2;
#pragma unroll
  for (int m = 16; m > 0; m >>= 1) {
#pragma unroll
    for (int p = 0; p < POS; p++)
      c[p] += __shfl_xor_sync(0xffffffffu, c[p], m);
  }
  if ((tid & 31) == 0) {
#pragma unroll
    for (int p = 0; p < POS; p++) red[p][tid >> 5] = c[p];
  }
  __syncthreads();
  if (tid < POS) {
    float s = b2[0];
#pragma unroll
    for (int w = 0; w < 8; w++) s += red[tid][w];
    g_fused[p0 + tid] = s;
  }
}

// ============================================================================
// Kernel 2: flash attention, mma.sync m16n8k16 + ldmatrix, fp16 2-term split.
// 4 warps, BM=64 (16 rows/warp), BN=64 keys/iter.
// ============================================================================
#define Bb 64
#define BNk 64
#define HSTR 36  // half2 row stride (32 data + 4 pad): 144B -> ldmatrix conflict-free

// smem offsets in 32-bit (half2) units
#define O_QHI 0
#define O_QLO (O_QHI + 64 * HSTR)
#define O_KHI (O_QLO + 64 * HSTR)
#define O_KLO (O_KHI + 64 * HSTR)
#define O_VHI (O_KLO + 64 * HSTR)
#define O_VLO (O_VHI + 64 * HSTR)
#define O_MK  (O_VLO + 64 * HSTR)
#define ATT_SMEM ((O_MK + 64) * 4)

#define MMA16816(d, a0, a1, a2, a3, b0, b1)                                 \
  asm volatile(                                                             \
      "mma.sync.aligned.m16n8k16.row.col.f32.f16.f16.f32 "                  \
      "{%0,%1,%2,%3}, {%4,%5,%6,%7}, {%8,%9}, {%0,%1,%2,%3};"               \
      : "+f"((d)[0]), "+f"((d)[1]), "+f"((d)[2]), "+f"((d)[3])              \
      : "r"(a0), "r"(a1), "r"(a2), "r"(a3), "r"(b0), "r"(b1))

#define LDMX4(r0, r1, r2, r3, addr)                                         \
  asm volatile(                                                             \
      "ldmatrix.sync.aligned.m8n8.x4.shared.b16 {%0,%1,%2,%3}, [%4];"       \
      : "=r"(r0), "=r"(r1), "=r"(r2), "=r"(r3) : "r"(addr))

#define LDMX4T(r0, r1, r2, r3, addr)                                        \
  asm volatile(                                                             \
      "ldmatrix.sync.aligned.m8n8.x4.trans.shared.b16 {%0,%1,%2,%3}, [%4];" \
      : "=r"(r0), "=r"(r1), "=r"(r2), "=r"(r3) : "r"(addr))

__device__ __forceinline__ uint32_t smem_u32(const void* p) {
  uint32_t a;
  asm("{ .reg .u64 t; cvta.to.shared.u64 t, %1; cvt.u32.u64 %0, t; }"
      : "=r"(a) : "l"(p));
  return a;
}
__device__ __forceinline__ void splitH2(float x0, float x1, uint32_t& hi,
                                        uint32_t& lo) {
  __half2 h = __floats2half2_rn(x0, x1);
  float2 hf = __half22float2(h);
  __half2 l = __floats2half2_rn(x0 - hf.x, x1 - hf.y);
  hi = *(uint32_t*)&h;
  lo = *(uint32_t*)&l;
}
__device__ __forceinline__ float ex2f(float x) {
  float r;
  asm("ex2.approx.ftz.f32 %0, %1;" : "=f"(r) : "f"(x));
  return r;
}

__global__ void __launch_bounds__(128, 4) attn_kernel(
    const float* __restrict__ qg, const float* __restrict__ kg,
    const float* __restrict__ vg, const float* __restrict__ at,
    float* __restrict__ out) {
  extern __shared__ uint32_t sm[];
  float* mk = (float*)(sm + O_MK);
  uint32_t sb = smem_u32(sm);

  int tid = threadIdx.x;
  int w = tid >> 5, lane = tid & 31;
  int quad = lane >> 2, four = lane & 3;
  int bh = blockIdx.y;
  int b = bh >> 4, h = bh & 15;
  int bx = (int)gridDim.x - 1 - (int)blockIdx.x;  // heaviest first
  int row0 = bx * Bb;

  const float sc = 0.125f * 1.44269504f;  // scale * log2(e)
  float alphaeff = at[h] * sc;

  // ---- load Q (scaled), split fp16 hi/lo, natural layout [r][e] ----
  {
    int r = tid >> 1;
    int e0 = (tid & 1) * 32;
    const float* src = qg + ((size_t)((b * LL + row0 + r) * HH + h)) * EE + e0;
    uint32_t* qh = sm + O_QHI + r * HSTR + (e0 >> 1);
    uint32_t* ql = sm + O_QLO + r * HSTR + (e0 >> 1);
#pragma unroll
    for (int u = 0; u < 8; u++) {
      float4 x = *(const float4*)(src + 4 * u);
      uint32_t h01, l01, h23, l23;
      splitH2(x.x * sc, x.y * sc, h01, l01);
      splitH2(x.z * sc, x.w * sc, h23, l23);
      qh[2 * u] = h01; qh[2 * u + 1] = h23;
      ql[2 * u] = l01; ql[2 * u + 1] = l23;
    }
  }
  __syncthreads();

  // ---- persistent Q A-fragments (kt-invariant): 8 ldmatrix.x4 ----
  uint32_t aqh[4][4], aql[4][4];
  {
    // A addressing: row = m0 + (lane&7) + ((lane&8)?8:0); k-half-ofs = (lane&16)?8:0
    int arow = 16 * w + (lane & 7) + ((lane >> 3) & 1) * 8;
    int acol = ((lane >> 4) & 1) * 4;  // u32 units
#pragma unroll
    for (int kk = 0; kk < 4; kk++) {
      uint32_t ah = sb + (uint32_t)(O_QHI + arow * HSTR + kk * 8 + acol) * 4;
      uint32_t al = sb + (uint32_t)(O_QLO + arow * HSTR + kk * 8 + acol) * 4;
      LDMX4(aqh[kk][0], aqh[kk][1], aqh[kk][2], aqh[kk][3], ah);
      LDMX4(aql[kk][0], aql[kk][1], aql[kk][2], aql[kk][3], al);
    }
  }

  // momentum for my two rows
  int r0g = row0 + 16 * w + quad;
  int r1g = r0g + 8;
  float mq0 = (r0g > 0) ? (g_fused[b * LL + r0g] - g_fused[b * LL + r0g - 1]) : 0.f;
  float mq1 = (g_fused[b * LL + r1g] - g_fused[b * LL + r1g - 1]);

  float oA[8][4];
#pragma unroll
  for (int nt = 0; nt < 8; nt++)
#pragma unroll
    for (int c = 0; c < 4; c++) oA[nt][c] = 0.f;
  float m0 = -CUDART_INF_F, m1 = -CUDART_INF_F, l0 = 0.f, l1 = 0.f;

  // B-frag (K, no-trans): row = 16p + (lane&7) + ((lane&16)?8:0); kofs = (lane&8)?8:0
  int krow = (lane & 7) + ((lane >> 4) & 1) * 8;
  int kcol = ((lane >> 3) & 1) * 4;  // u32
  // B-frag (V, trans): row(s) = 16t + (lane&7) + ((lane&8)?8:0); dofs = (lane&16)?8:0
  int vrow = (lane & 7) + ((lane >> 3) & 1) * 8;
  int vcol = ((lane >> 4) & 1) * 4;  // u32

  int ntiles = bx + 1;
  for (int kt = 0; kt < ntiles; kt++) {
    int c0 = kt * BNk;
    __syncthreads();  // safe to overwrite K/V

    // ---- load K hi/lo (natural [key][e]) ----
    {
      int r = tid >> 1;
      int e0 = (tid & 1) * 32;
      const float* src = kg + ((size_t)((b * LL + c0 + r) * HH + h)) * EE + e0;
      uint32_t* kh = sm + O_KHI + r * HSTR + (e0 >> 1);
      uint32_t* kl = sm + O_KLO + r * HSTR + (e0 >> 1);
#pragma unroll
      for (int u = 0; u < 8; u++) {
        float4 x = *(const float4*)(src + 4 * u);
        uint32_t h01, l01, h23, l23;
        splitH2(x.x, x.y, h01, l01);
        splitH2(x.z, x.w, h23, l23);
        kh[2 * u] = h01; kh[2 * u + 1] = h23;
        kl[2 * u] = l01; kl[2 * u + 1] = l23;
      }
    }
    // ---- load V hi/lo (natural [s][d]; trans happens in ldmatrix) ----
    {
      int r = tid >> 1;
      int d0 = (tid & 1) * 32;
      const float* src = vg + ((size_t)((b * LL + c0 + r) * HH + h)) * DD + d0;
      uint32_t* vh = sm + O_VHI + r * HSTR + (d0 >> 1);
      uint32_t* vl = sm + O_VLO + r * HSTR + (d0 >> 1);
#pragma unroll
      for (int u = 0; u < 8; u++) {
        float4 x = *(const float4*)(src + 4 * u);
        uint32_t h01, l01, h23, l23;
        splitH2(x.x, x.y, h01, l01);
        splitH2(x.z, x.w, h23, l23);
        vh[2 * u] = h01; vh[2 * u + 1] = h23;
        vl[2 * u] = l01; vl[2 * u + 1] = l23;
      }
    }
    if (tid < BNk) {
      int l = c0 + tid;
      mk[tid] = (l > 0) ? (g_fused[b * LL + l] - g_fused[b * LL + l - 1]) : 0.f;
    }
    __syncthreads();

    // ---- S = Q K^T : per n-pair p, per kk: 2 ldmatrix.x4 + 6 MMAs ----
    float sA[8][4];
#pragma unroll
    for (int nt = 0; nt < 8; nt++)
#pragma unroll
      for (int c = 0; c < 4; c++) sA[nt][c] = 0.f;

#pragma unroll
    for (int p = 0; p < 4; p++) {
      int rb = (16 * p + krow) * HSTR + kcol;
#pragma unroll
      for (int kk = 0; kk < 4; kk++) {
        uint32_t bh0, bh1, bh2, bh3, bl0, bl1, bl2, bl3;
        uint32_t ah = sb + (uint32_t)(O_KHI + rb + kk * 8) * 4;
        uint32_t al = sb + (uint32_t)(O_KLO + rb + kk * 8) * 4;
        LDMX4(bh0, bh1, bh2, bh3, ah);
        LDMX4(bl0, bl1, bl2, bl3, al);
        MMA16816(sA[2 * p], aqh[kk][0], aqh[kk][1], aqh[kk][2], aqh[kk][3], bh0, bh1);
        MMA16816(sA[2 * p], aqh[kk][0], aqh[kk][1], aqh[kk][2], aqh[kk][3], bl0, bl1);
        MMA16816(sA[2 * p], aql[kk][0], aql[kk][1], aql[kk][2], aql[kk][3], bh0, bh1);
        MMA16816(sA[2 * p + 1], aqh[kk][0], aqh[kk][1], aqh[kk][2], aqh[kk][3], bh2, bh3);
        MMA16816(sA[2 * p + 1], aqh[kk][0], aqh[kk][1], aqh[kk][2], aqh[kk][3], bl2, bl3);
        MMA16816(sA[2 * p + 1], aql[kk][0], aql[kk][1], aql[kk][2], aql[kk][3], bh2, bh3);
      }
    }

    // ---- bias + causal mask + online softmax (base-2) ----
    float mx0 = -CUDART_INF_F, mx1 = -CUDART_INF_F;
    bool diag = (kt == bx);
#pragma unroll
    for (int nt = 0; nt < 8; nt++) {
      int cA = nt * 8 + four * 2;
      float mkA = mk[cA], mkB = mk[cA + 1];
      float x0 = sA[nt][0] - alphaeff * fabsf(mq0 - mkA);
      float x1 = sA[nt][1] - alphaeff * fabsf(mq0 - mkB);
      float x2 = sA[nt][2] - alphaeff * fabsf(mq1 - mkA);
      float x3 = sA[nt][3] - alphaeff * fabsf(mq1 - mkB);
      if (diag) {
        int cg = c0 + cA;
        x0 = (cg <= r0g) ? x0 : -CUDART_INF_F;
        x1 = (cg + 1 <= r0g) ? x1 : -CUDART_INF_F;
        x2 = (cg <= r1g) ? x2 : -CUDART_INF_F;
        x3 = (cg + 1 <= r1g) ? x3 : -CUDART_INF_F;
      }
      sA[nt][0] = x0; sA[nt][1] = x1; sA[nt][2] = x2; sA[nt][3] = x3;
      mx0 = fmaxf(mx0, fmaxf(x0, x1));
      mx1 = fmaxf(mx1, fmaxf(x2, x3));
    }
    mx0 = fmaxf(mx0, __shfl_xor_sync(0xffffffffu, mx0, 1));
    mx0 = fmaxf(mx0, __shfl_xor_sync(0xffffffffu, mx0, 2));
    mx1 = fmaxf(mx1, __shfl_xor_sync(0xffffffffu, mx1, 1));
    mx1 = fmaxf(mx1, __shfl_xor_sync(0xffffffffu, mx1, 2));

    float mn0 = fmaxf(m0, mx0), mn1 = fmaxf(m1, mx1);
    float al0 = ex2f(m0 - mn0), al1 = ex2f(m1 - mn1);
    m0 = mn0; m1 = mn1;

    float rs0 = 0.f, rs1 = 0.f;
#pragma unroll
    for (int nt = 0; nt < 8; nt++) {
      float e0v = ex2f(sA[nt][0] - mn0);
      float e1v = ex2f(sA[nt][1] - mn0);
      float e2v = ex2f(sA[nt][2] - mn1);
      float e3v = ex2f(sA[nt][3] - mn1);
      sA[nt][0] = e0v; sA[nt][1] = e1v; sA[nt][2] = e2v; sA[nt][3] = e3v;
      rs0 += e0v + e1v;
      rs1 += e2v + e3v;
    }
    rs0 += __shfl_xor_sync(0xffffffffu, rs0, 1);
    rs0 += __shfl_xor_sync(0xffffffffu, rs0, 2);
    rs1 += __shfl_xor_sync(0xffffffffu, rs1, 1);
    rs1 += __shfl_xor_sync(0xffffffffu, rs1, 2);
    l0 = l0 * al0 + rs0;
    l1 = l1 * al1 + rs1;

    // rescale O
#pragma unroll
    for (int nt = 0; nt < 8; nt++) {
      oA[nt][0] *= al0; oA[nt][1] *= al0;
      oA[nt][2] *= al1; oA[nt][3] *= al1;
    }

    // ---- pack P fragments (A of PV) in registers ----
    uint32_t ph[4][4], pl[4][4];
#pragma unroll
    for (int t = 0; t < 4; t++) {
      splitH2(sA[2 * t][0], sA[2 * t][1], ph[t][0], pl[t][0]);
      splitH2(sA[2 * t][2], sA[2 * t][3], ph[t][1], pl[t][1]);
      splitH2(sA[2 * t + 1][0], sA[2 * t + 1][1], ph[t][2], pl[t][2]);
      splitH2(sA[2 * t + 1][2], sA[2 * t + 1][3], ph[t][3], pl[t][3]);
    }

    // ---- O += P V : per d-pair p, per s-tile t: 2 ldmatrix.x4.trans + 6 MMAs ----
#pragma unroll
    for (int p = 0; p < 4; p++) {
#pragma unroll
      for (int t = 0; t < 4; t++) {
        uint32_t bh0, bh1, bh2, bh3, bl0, bl1, bl2, bl3;
        int rb = (16 * t + vrow) * HSTR + 8 * p + vcol;
        uint32_t ah = sb + (uint32_t)(O_VHI + rb) * 4;
        uint32_t al = sb + (uint32_t)(O_VLO + rb) * 4;
        LDMX4T(bh0, bh1, bh2, bh3, ah);
        LDMX4T(bl0, bl1, bl2, bl3, al);
        MMA16816(oA[2 * p], ph[t][0], ph[t][1], ph[t][2], ph[t][3], bh0, bh1);
        MMA16816(oA[2 * p], ph[t][0], ph[t][1], ph[t][2], ph[t][3], bl0, bl1);
        MMA16816(oA[2 * p], pl[t][0], pl[t][1], pl[t][2], pl[t][3], bh0, bh1);
        MMA16816(oA[2 * p + 1], ph[t][0], ph[t][1], ph[t][2], ph[t][3], bh2, bh3);
        MMA16816(oA[2 * p + 1], ph[t][0], ph[t][1], ph[t][2], ph[t][3], bl2, bl3);
        MMA16816(oA[2 * p + 1], pl[t][0], pl[t][1], pl[t][2], pl[t][3], bh2, bh3);
      }
    }
  }

  // ---- epilogue ----
  float inv0 = 1.f / l0, inv1 = 1.f / l1;
  float* d0p = out + ((size_t)((b * LL + r0g) * HH + h)) * DD;
  float* d1p = out + ((size_t)((b * LL + r1g) * HH + h)) * DD;
#pragma unroll
  for (int nt = 0; nt < 8; nt++) {
    int c = nt * 8 + four * 2;
    *(float2*)(d0p + c) = make_float2(oA[nt][0] * inv0, oA[nt][1] * inv0);
    *(float2*)(d1p + c) = make_float2(oA[nt][2] * inv1, oA[nt][3] * inv1);
  }
}

// ---------------------------------------------------------------------------
extern "C" void kernel_launch(void* const* d_in, const int* in_sizes, int n_in,
                              void* d_out, int out_size) {
  const float* q = (const float*)d_in[0];
  const float* k = (const float*)d_in[1];
  const float* v = (const float*)d_in[2];
  const float* raw = (const float*)d_in[3];
  const float* w1 = (const float*)d_in[4];
  const float* b1 = (const float*)d_in[5];
  const float* w2 = (const float*)d_in[6];
  const float* b2 = (const float*)d_in[7];
  const float* at = (const float*)d_in[8];
  float* out = (float*)d_out;

  mlp_kernel<<<(BB * LL) / POS, 256>>>(raw, w1, b1, w2, b2);

  cudaFuncSetAttribute(attn_kernel, cudaFuncAttributeMaxDynamicSharedMemorySize,
                       ATT_SMEM);
  dim3 grid(LL / Bb, BB * HH);
  attn_kernel<<<grid, 128, ATT_SMEM>>>(q, k, v, at, out);
}

// round 7
// speedup vs baseline: 2.1729x; 1.1049x over previous
#include <cuda_runtime.h>
#include <cuda_fp16.h>
#include <math_constants.h>
#include <cstdint>

// Problem shape (fixed)
#define BB 2
#define LL 2048
#define HH 16
#define EE 64
#define DD 64
#define DMODEL 512
#define DHID 256

__device__ float g_fused[BB * LL];

// ============================================================================
// Kernel 1: fused MLP (unchanged — not the bottleneck)
// ============================================================================
#define POS 16
#define RSTR 20

__global__ __launch_bounds__(256) void mlp_kernel(
    const float* __restrict__ raw,
    const float* __restrict__ w1, const float* __restrict__ b1,
    const float* __restrict__ w2, const float* __restrict__ b2) {
  __shared__ float rawT[DMODEL * RSTR];
  __shared__ float red[POS][9];
  int tid = threadIdx.x;
  int p0 = blockIdx.x * POS;

#pragma unroll
  for (int it = 0; it < 8; it++) {
    int f = tid + 256 * it;
    int p = f >> 7;
    int i4 = f & 127;
    float4 x = *(const float4*)(raw + (size_t)(p0 + p) * DMODEL + i4 * 4);
    rawT[(i4 * 4 + 0) * RSTR + p] = x.x;
    rawT[(i4 * 4 + 1) * RSTR + p] = x.y;
    rawT[(i4 * 4 + 2) * RSTR + p] = x.z;
    rawT[(i4 * 4 + 3) * RSTR + p] = x.w;
  }
  __syncthreads();

  int j = tid;
  float acc[POS];
#pragma unroll
  for (int p = 0; p < POS; p++) acc[p] = 0.f;

#pragma unroll 4
  for (int i = 0; i < DMODEL; i++) {
    float w = __ldg(w1 + (size_t)i * DHID + j);
    const float4* rp = (const float4*)(rawT + i * RSTR);
    float4 r0 = rp[0], r1 = rp[1], r2 = rp[2], r3 = rp[3];
    acc[0] = fmaf(w, r0.x, acc[0]);   acc[1] = fmaf(w, r0.y, acc[1]);
    acc[2] = fmaf(w, r0.z, acc[2]);   acc[3] = fmaf(w, r0.w, acc[3]);
    acc[4] = fmaf(w, r1.x, acc[4]);   acc[5] = fmaf(w, r1.y, acc[5]);
    acc[6] = fmaf(w, r1.z, acc[6]);   acc[7] = fmaf(w, r1.w, acc[7]);
    acc[8] = fmaf(w, r2.x, acc[8]);   acc[9] = fmaf(w, r2.y, acc[9]);
    acc[10] = fmaf(w, r2.z, acc[10]); acc[11] = fmaf(w, r2.w, acc[11]);
    acc[12] = fmaf(w, r3.x, acc[12]); acc[13] = fmaf(w, r3.y, acc[13]);
    acc[14] = fmaf(w, r3.z, acc[14]); acc[15] = fmaf(w, r3.w, acc[15]);
  }

  float bb1 = b1[j];
  float ww2 = w2[j];
  float c[POS];
#pragma unroll
  for (int p = 0; p < POS; p++) c[p] = fmaxf(acc[p] + bb1, 0.f) * ww2;
#pragma unroll
  for (int m = 16; m > 0; m >>= 1) {
#pragma unroll
    for (int p = 0; p < POS; p++)
      c[p] += __shfl_xor_sync(0xffffffffu, c[p], m);
  }
  if ((tid & 31) == 0) {
#pragma unroll
    for (int p = 0; p < POS; p++) red[p][tid >> 5] = c[p];
  }
  __syncthreads();
  if (tid < POS) {
    float s = b2[0];
#pragma unroll
    for (int w = 0; w < 8; w++) s += red[tid][w];
    g_fused[p0 + tid] = s;
  }
}

// ============================================================================
// Kernel 2: flash attention, mma.sync m16n8k16 + ldmatrix, fp16 2-term split.
// 4 warps, BM=64 (16 rows/warp), BN=64 keys/iter.
// Loop order kk/t-outer so all 8 accumulator chains interleave (ILP).
// ============================================================================
#define Bb 64
#define BNk 64
#define HSTR 36  // half2 row stride (32 data + 4 pad)

// smem offsets in 32-bit (half2) units
#define O_QHI 0
#define O_QLO (O_QHI + 64 * HSTR)
#define O_KHI (O_QLO + 64 * HSTR)
#define O_KLO (O_KHI + 64 * HSTR)
#define O_VHI (O_KLO + 64 * HSTR)
#define O_VLO (O_VHI + 64 * HSTR)
#define O_MK  (O_VLO + 64 * HSTR)
#define ATT_SMEM ((O_MK + 64) * 4)

#define MMA16816(d, a0, a1, a2, a3, b0, b1)                                 \
  asm volatile(                                                             \
      "mma.sync.aligned.m16n8k16.row.col.f32.f16.f16.f32 "                  \
      "{%0,%1,%2,%3}, {%4,%5,%6,%7}, {%8,%9}, {%0,%1,%2,%3};"               \
      : "+f"((d)[0]), "+f"((d)[1]), "+f"((d)[2]), "+f"((d)[3])              \
      : "r"(a0), "r"(a1), "r"(a2), "r"(a3), "r"(b0), "r"(b1))

#define LDMX4(r0, r1, r2, r3, addr)                                         \
  asm volatile(                                                             \
      "ldmatrix.sync.aligned.m8n8.x4.shared.b16 {%0,%1,%2,%3}, [%4];"       \
      : "=r"(r0), "=r"(r1), "=r"(r2), "=r"(r3) : "r"(addr))

#define LDMX4T(r0, r1, r2, r3, addr)                                        \
  asm volatile(                                                             \
      "ldmatrix.sync.aligned.m8n8.x4.trans.shared.b16 {%0,%1,%2,%3}, [%4];" \
      : "=r"(r0), "=r"(r1), "=r"(r2), "=r"(r3) : "r"(addr))

__device__ __forceinline__ uint32_t smem_u32(const void* p) {
  uint32_t a;
  asm("{ .reg .u64 t; cvta.to.shared.u64 t, %1; cvt.u32.u64 %0, t; }"
      : "=r"(a) : "l"(p));
  return a;
}
__device__ __forceinline__ void splitH2(float x0, float x1, uint32_t& hi,
                                        uint32_t& lo) {
  __half2 h = __floats2half2_rn(x0, x1);
  float2 hf = __half22float2(h);
  __half2 l = __floats2half2_rn(x0 - hf.x, x1 - hf.y);
  hi = *(uint32_t*)&h;
  lo = *(uint32_t*)&l;
}
__device__ __forceinline__ float ex2f(float x) {
  float r;
  asm("ex2.approx.ftz.f32 %0, %1;" : "=f"(r) : "f"(x));
  return r;
}

__global__ void __launch_bounds__(128, 4) attn_kernel(
    const float* __restrict__ qg, const float* __restrict__ kg,
    const float* __restrict__ vg, const float* __restrict__ at,
    float* __restrict__ out) {
  extern __shared__ uint32_t sm[];
  float* mk = (float*)(sm + O_MK);
  uint32_t sb = smem_u32(sm);

  int tid = threadIdx.x;
  int w = tid >> 5, lane = tid & 31;
  int quad = lane >> 2, four = lane & 3;
  int bh = blockIdx.y;
  int b = bh >> 4, h = bh & 15;
  int bx = (int)gridDim.x - 1 - (int)blockIdx.x;  // heaviest first
  int row0 = bx * Bb;

  const float sc = 0.125f * 1.44269504f;  // scale * log2(e)
  float alphaeff = at[h] * sc;

  // ---- load Q (scaled), split fp16 hi/lo, natural layout [r][e] ----
  {
    int r = tid >> 1;
    int e0 = (tid & 1) * 32;
    const float* src = qg + ((size_t)((b * LL + row0 + r) * HH + h)) * EE + e0;
    uint32_t* qh = sm + O_QHI + r * HSTR + (e0 >> 1);
    uint32_t* ql = sm + O_QLO + r * HSTR + (e0 >> 1);
#pragma unroll
    for (int u = 0; u < 8; u++) {
      float4 x = *(const float4*)(src + 4 * u);
      uint32_t h01, l01, h23, l23;
      splitH2(x.x * sc, x.y * sc, h01, l01);
      splitH2(x.z * sc, x.w * sc, h23, l23);
      qh[2 * u] = h01; qh[2 * u + 1] = h23;
      ql[2 * u] = l01; ql[2 * u + 1] = l23;
    }
  }

  // fragment smem addresses (byte)
  int arow = 16 * w + (lane & 7) + ((lane >> 3) & 1) * 8;
  int acol = ((lane >> 4) & 1) * 4;
  uint32_t aq_addr = sb + (uint32_t)(O_QHI + arow * HSTR + acol) * 4;
  int krow = (lane & 7) + ((lane >> 4) & 1) * 8;
  int kcol = ((lane >> 3) & 1) * 4;
  uint32_t kb_addr = sb + (uint32_t)(O_KHI + krow * HSTR + kcol) * 4;
  int vrow = (lane & 7) + ((lane >> 3) & 1) * 8;
  int vcol = ((lane >> 4) & 1) * 4;
  uint32_t vb_addr = sb + (uint32_t)(O_VHI + vrow * HSTR + vcol) * 4;
  const uint32_t HL = (uint32_t)(64 * HSTR) * 4;  // hi->lo offset bytes

  // momentum for my two rows
  int r0g = row0 + 16 * w + quad;
  int r1g = r0g + 8;
  float mq0 = (r0g > 0) ? (g_fused[b * LL + r0g] - g_fused[b * LL + r0g - 1]) : 0.f;
  float mq1 = (g_fused[b * LL + r1g] - g_fused[b * LL + r1g - 1]);

  float oA[8][4];
#pragma unroll
  for (int nt = 0; nt < 8; nt++)
#pragma unroll
    for (int c = 0; c < 4; c++) oA[nt][c] = 0.f;
  float m0 = -CUDART_INF_F, m1 = -CUDART_INF_F, l0 = 0.f, l1 = 0.f;

  int ntiles = bx + 1;
  for (int kt = 0; kt < ntiles; kt++) {
    int c0 = kt * BNk;
    __syncthreads();  // safe to overwrite K/V (covers Q write on kt=0)

    // ---- load K hi/lo (natural [key][e]) ----
    {
      int r = tid >> 1;
      int e0 = (tid & 1) * 32;
      const float* src = kg + ((size_t)((b * LL + c0 + r) * HH + h)) * EE + e0;
      uint32_t* kh = sm + O_KHI + r * HSTR + (e0 >> 1);
      uint32_t* kl = sm + O_KLO + r * HSTR + (e0 >> 1);
#pragma unroll
      for (int u = 0; u < 8; u++) {
        float4 x = *(const float4*)(src + 4 * u);
        uint32_t h01, l01, h23, l23;
        splitH2(x.x, x.y, h01, l01);
        splitH2(x.z, x.w, h23, l23);
        kh[2 * u] = h01; kh[2 * u + 1] = h23;
        kl[2 * u] = l01; kl[2 * u + 1] = l23;
      }
    }
    // ---- load V hi/lo (natural [s][d]; trans in ldmatrix) ----
    {
      int r = tid >> 1;
      int d0 = (tid & 1) * 32;
      const float* src = vg + ((size_t)((b * LL + c0 + r) * HH + h)) * DD + d0;
      uint32_t* vh = sm + O_VHI + r * HSTR + (d0 >> 1);
      uint32_t* vl = sm + O_VLO + r * HSTR + (d0 >> 1);
#pragma unroll
      for (int u = 0; u < 8; u++) {
        float4 x = *(const float4*)(src + 4 * u);
        uint32_t h01, l01, h23, l23;
        splitH2(x.x, x.y, h01, l01);
        splitH2(x.z, x.w, h23, l23);
        vh[2 * u] = h01; vh[2 * u + 1] = h23;
        vl[2 * u] = l01; vl[2 * u + 1] = l23;
      }
    }
    if (tid < BNk) {
      int l = c0 + tid;
      mk[tid] = (l > 0) ? (g_fused[b * LL + l] - g_fused[b * LL + l - 1]) : 0.f;
    }
    __syncthreads();

    // ---- S = Q K^T : kk-outer, 8 interleaved accumulator chains ----
    float sA[8][4];
#pragma unroll
    for (int nt = 0; nt < 8; nt++)
#pragma unroll
      for (int c = 0; c < 4; c++) sA[nt][c] = 0.f;

#pragma unroll
    for (int kk = 0; kk < 4; kk++) {
      uint32_t aqh[4], aql[4];
      LDMX4(aqh[0], aqh[1], aqh[2], aqh[3], aq_addr + kk * 32);
      LDMX4(aql[0], aql[1], aql[2], aql[3], aq_addr + kk * 32 + HL);
      uint32_t bhf[4][4], blf[4][4];
#pragma unroll
      for (int p = 0; p < 4; p++) {
        uint32_t ka = kb_addr + (uint32_t)(16 * p * HSTR + kk * 8) * 4;
        LDMX4(bhf[p][0], bhf[p][1], bhf[p][2], bhf[p][3], ka);
        LDMX4(blf[p][0], blf[p][1], blf[p][2], blf[p][3], ka + HL);
      }
      // phase hh: all 8 accums
#pragma unroll
      for (int p = 0; p < 4; p++) {
        MMA16816(sA[2 * p], aqh[0], aqh[1], aqh[2], aqh[3], bhf[p][0], bhf[p][1]);
        MMA16816(sA[2 * p + 1], aqh[0], aqh[1], aqh[2], aqh[3], bhf[p][2], bhf[p][3]);
      }
      // phase hl
#pragma unroll
      for (int p = 0; p < 4; p++) {
        MMA16816(sA[2 * p], aqh[0], aqh[1], aqh[2], aqh[3], blf[p][0], blf[p][1]);
        MMA16816(sA[2 * p + 1], aqh[0], aqh[1], aqh[2], aqh[3], blf[p][2], blf[p][3]);
      }
      // phase lh
#pragma unroll
      for (int p = 0; p < 4; p++) {
        MMA16816(sA[2 * p], aql[0], aql[1], aql[2], aql[3], bhf[p][0], bhf[p][1]);
        MMA16816(sA[2 * p + 1], aql[0], aql[1], aql[2], aql[3], bhf[p][2], bhf[p][3]);
      }
    }

    // ---- bias + causal mask + online softmax (base-2) ----
    float mx0 = -CUDART_INF_F, mx1 = -CUDART_INF_F;
    bool diag = (kt == bx);
#pragma unroll
    for (int nt = 0; nt < 8; nt++) {
      int cA = nt * 8 + four * 2;
      float mkA = mk[cA], mkB = mk[cA + 1];
      float x0 = sA[nt][0] - alphaeff * fabsf(mq0 - mkA);
      float x1 = sA[nt][1] - alphaeff * fabsf(mq0 - mkB);
      float x2 = sA[nt][2] - alphaeff * fabsf(mq1 - mkA);
      float x3 = sA[nt][3] - alphaeff * fabsf(mq1 - mkB);
      if (diag) {
        int cg = c0 + cA;
        x0 = (cg <= r0g) ? x0 : -CUDART_INF_F;
        x1 = (cg + 1 <= r0g) ? x1 : -CUDART_INF_F;
        x2 = (cg <= r1g) ? x2 : -CUDART_INF_F;
        x3 = (cg + 1 <= r1g) ? x3 : -CUDART_INF_F;
      }
      sA[nt][0] = x0; sA[nt][1] = x1; sA[nt][2] = x2; sA[nt][3] = x3;
      mx0 = fmaxf(mx0, fmaxf(x0, x1));
      mx1 = fmaxf(mx1, fmaxf(x2, x3));
    }
    mx0 = fmaxf(mx0, __shfl_xor_sync(0xffffffffu, mx0, 1));
    mx0 = fmaxf(mx0, __shfl_xor_sync(0xffffffffu, mx0, 2));
    mx1 = fmaxf(mx1, __shfl_xor_sync(0xffffffffu, mx1, 1));
    mx1 = fmaxf(mx1, __shfl_xor_sync(0xffffffffu, mx1, 2));

    float mn0 = fmaxf(m0, mx0), mn1 = fmaxf(m1, mx1);
    float al0 = ex2f(m0 - mn0), al1 = ex2f(m1 - mn1);
    m0 = mn0; m1 = mn1;

    float rs0 = 0.f, rs1 = 0.f;
#pragma unroll
    for (int nt = 0; nt < 8; nt++) {
      float e0v = ex2f(sA[nt][0] - mn0);
      float e1v = ex2f(sA[nt][1] - mn0);
      float e2v = ex2f(sA[nt][2] - mn1);
      float e3v = ex2f(sA[nt][3] - mn1);
      sA[nt][0] = e0v; sA[nt][1] = e1v; sA[nt][2] = e2v; sA[nt][3] = e3v;
      rs0 += e0v + e1v;
      rs1 += e2v + e3v;
    }
    rs0 += __shfl_xor_sync(0xffffffffu, rs0, 1);
    rs0 += __shfl_xor_sync(0xffffffffu, rs0, 2);
    rs1 += __shfl_xor_sync(0xffffffffu, rs1, 1);
    rs1 += __shfl_xor_sync(0xffffffffu, rs1, 2);
    l0 = l0 * al0 + rs0;
    l1 = l1 * al1 + rs1;

    // rescale O
#pragma unroll
    for (int nt = 0; nt < 8; nt++) {
      oA[nt][0] *= al0; oA[nt][1] *= al0;
      oA[nt][2] *= al1; oA[nt][3] *= al1;
    }

    // ---- pack P fragments (A of PV) ----
    uint32_t ph[4][4], pl[4][4];
#pragma unroll
    for (int t = 0; t < 4; t++) {
      splitH2(sA[2 * t][0], sA[2 * t][1], ph[t][0], pl[t][0]);
      splitH2(sA[2 * t][2], sA[2 * t][3], ph[t][1], pl[t][1]);
      splitH2(sA[2 * t + 1][0], sA[2 * t + 1][1], ph[t][2], pl[t][2]);
      splitH2(sA[2 * t + 1][2], sA[2 * t + 1][3], ph[t][3], pl[t][3]);
    }

    // ---- O += P V : t-outer, 8 interleaved accumulator chains ----
#pragma unroll
    for (int t = 0; t < 4; t++) {
      uint32_t vhf[4][4], vlf[4][4];
#pragma unroll
      for (int p = 0; p < 4; p++) {
        uint32_t va = vb_addr + (uint32_t)(16 * t * HSTR + 8 * p) * 4;
        LDMX4T(vhf[p][0], vhf[p][1], vhf[p][2], vhf[p][3], va);
        LDMX4T(vlf[p][0], vlf[p][1], vlf[p][2], vlf[p][3], va + HL);
      }
#pragma unroll
      for (int p = 0; p < 4; p++) {
        MMA16816(oA[2 * p], ph[t][0], ph[t][1], ph[t][2], ph[t][3], vhf[p][0], vhf[p][1]);
        MMA16816(oA[2 * p + 1], ph[t][0], ph[t][1], ph[t][2], ph[t][3], vhf[p][2], vhf[p][3]);
      }
#pragma unroll
      for (int p = 0; p < 4; p++) {
        MMA16816(oA[2 * p], ph[t][0], ph[t][1], ph[t][2], ph[t][3], vlf[p][0], vlf[p][1]);
        MMA16816(oA[2 * p + 1], ph[t][0], ph[t][1], ph[t][2], ph[t][3], vlf[p][2], vlf[p][3]);
      }
#pragma unroll
      for (int p = 0; p < 4; p++) {
        MMA16816(oA[2 * p], pl[t][0], pl[t][1], pl[t][2], pl[t][3], vhf[p][0], vhf[p][1]);
        MMA16816(oA[2 * p + 1], pl[t][0], pl[t][1], pl[t][2], pl[t][3], vhf[p][2], vhf[p][3]);
      }
    }
  }

  // ---- epilogue ----
  float inv0 = 1.f / l0, inv1 = 1.f / l1;
  float* d0p = out + ((size_t)((b * LL + r0g) * HH + h)) * DD;
  float* d1p = out + ((size_t)((b * LL + r1g) * HH + h)) * DD;
#pragma unroll
  for (int nt = 0; nt < 8; nt++) {
    int c = nt * 8 + four * 2;
    *(float2*)(d0p + c) = make_float2(oA[nt][0] * inv0, oA[nt][1] * inv0);
    *(float2*)(d1p + c) = make_float2(oA[nt][2] * inv1, oA[nt][3] * inv1);
  }
}

// ---------------------------------------------------------------------------
extern "C" void kernel_launch(void* const* d_in, const int* in_sizes, int n_in,
                              void* d_out, int out_size) {
  const float* q = (const float*)d_in[0];
  const float* k = (const float*)d_in[1];
  const float* v = (const float*)d_in[2];
  const float* raw = (const float*)d_in[3];
  const float* w1 = (const float*)d_in[4];
  const float* b1 = (const float*)d_in[5];
  const float* w2 = (const float*)d_in[6];
  const float* b2 = (const float*)d_in[7];
  const float* at = (const float*)d_in[8];
  float* out = (float*)d_out;

  mlp_kernel<<<(BB * LL) / POS, 256>>>(raw, w1, b1, w2, b2);

  cudaFuncSetAttribute(attn_kernel, cudaFuncAttributeMaxDynamicSharedMemorySize,
                       ATT_SMEM);
  dim3 grid(LL / Bb, BB * HH);
  attn_kernel<<<grid, 128, ATT_SMEM>>>(q, k, v, at, out);
}

// round 9
// speedup vs baseline: 3.0304x; 1.3947x over previous
#include <cuda_runtime.h>
#include <cuda_fp16.h>
#include <math_constants.h>
#include <cstdint>

// Problem shape (fixed)
#define BB 2
#define LL 2048
#define HH 16
#define EE 64
#define DD 64
#define DMODEL 512
#define DHID 256

__device__ float g_fused[BB * LL];

// ============================================================================
// Kernel 1: fused MLP (unchanged — not the bottleneck)
// ============================================================================
#define POS 16
#define RSTR 20

__global__ __launch_bounds__(256) void mlp_kernel(
    const float* __restrict__ raw,
    const float* __restrict__ w1, const float* __restrict__ b1,
    const float* __restrict__ w2, const float* __restrict__ b2) {
  __shared__ float rawT[DMODEL * RSTR];
  __shared__ float red[POS][9];
  int tid = threadIdx.x;
  int p0 = blockIdx.x * POS;

#pragma unroll
  for (int it = 0; it < 8; it++) {
    int f = tid + 256 * it;
    int p = f >> 7;
    int i4 = f & 127;
    float4 x = *(const float4*)(raw + (size_t)(p0 + p) * DMODEL + i4 * 4);
    rawT[(i4 * 4 + 0) * RSTR + p] = x.x;
    rawT[(i4 * 4 + 1) * RSTR + p] = x.y;
    rawT[(i4 * 4 + 2) * RSTR + p] = x.z;
    rawT[(i4 * 4 + 3) * RSTR + p] = x.w;
  }
  __syncthreads();

  int j = tid;
  float acc[POS];
#pragma unroll
  for (int p = 0; p < POS; p++) acc[p] = 0.f;

#pragma unroll 4
  for (int i = 0; i < DMODEL; i++) {
    float w = __ldg(w1 + (size_t)i * DHID + j);
    const float4* rp = (const float4*)(rawT + i * RSTR);
    float4 r0 = rp[0], r1 = rp[1], r2 = rp[2], r3 = rp[3];
    acc[0] = fmaf(w, r0.x, acc[0]);   acc[1] = fmaf(w, r0.y, acc[1]);
    acc[2] = fmaf(w, r0.z, acc[2]);   acc[3] = fmaf(w, r0.w, acc[3]);
    acc[4] = fmaf(w, r1.x, acc[4]);   acc[5] = fmaf(w, r1.y, acc[5]);
    acc[6] = fmaf(w, r1.z, acc[6]);   acc[7] = fmaf(w, r1.w, acc[7]);
    acc[8] = fmaf(w, r2.x, acc[8]);   acc[9] = fmaf(w, r2.y, acc[9]);
    acc[10] = fmaf(w, r2.z, acc[10]); acc[11] = fmaf(w, r2.w, acc[11]);
    acc[12] = fmaf(w, r3.x, acc[12]); acc[13] = fmaf(w, r3.y, acc[13]);
    acc[14] = fmaf(w, r3.z, acc[14]); acc[15] = fmaf(w, r3.w, acc[15]);
  }

  float bb1 = b1[j];
  float ww2 = w2[j];
  float c[POS];
#pragma unroll
  for (int p = 0; p < POS; p++) c[p] = fmaxf(acc[p] + bb1, 0.f) * ww2;
#pragma unroll
  for (int m = 16; m > 0; m >>= 1) {
#pragma unroll
    for (int p = 0; p < POS; p++)
      c[p] += __shfl_xor_sync(0xffffffffu, c[p], m);
  }
  if ((tid & 31) == 0) {
#pragma unroll
    for (int p = 0; p < POS; p++) red[p][tid >> 5] = c[p];
  }
  __syncthreads();
  if (tid < POS) {
    float s = b2[0];
#pragma unroll
    for (int w = 0; w < 8; w++) s += red[tid][w];
    g_fused[p0 + tid] = s;
  }
}

// ============================================================================
// Kernel 2: flash attention, mma.sync m16n8k16 + ldmatrix + XOR swizzle.
// 2-term fp16 split (A-hi only: hh + hl). 8 warps, BM=128, BN=64.
// ============================================================================
#define Bb 128
#define BNk 64

// smem offsets in u32 units; each array row = 32 u32 (128B = 8 swizzle chunks)
#define O_QHI 0
#define O_KHI 4096
#define O_KLO 6144
#define O_VHI 8192
#define O_VLO 10240
#define O_MK  12288
#define ATT_SMEM ((12288 + 64) * 4)

#define MMA16816(d, a0, a1, a2, a3, b0, b1)                                 \
  asm volatile(                                                             \
      "mma.sync.aligned.m16n8k16.row.col.f32.f16.f16.f32 "                  \
      "{%0,%1,%2,%3}, {%4,%5,%6,%7}, {%8,%9}, {%0,%1,%2,%3};"               \
      : "+f"((d)[0]), "+f"((d)[1]), "+f"((d)[2]), "+f"((d)[3])              \
      : "r"(a0), "r"(a1), "r"(a2), "r"(a3), "r"(b0), "r"(b1))

#define LDMX4(r0, r1, r2, r3, addr)                                         \
  asm volatile(                                                             \
      "ldmatrix.sync.aligned.m8n8.x4.shared.b16 {%0,%1,%2,%3}, [%4];"       \
      : "=r"(r0), "=r"(r1), "=r"(r2), "=r"(r3) : "r"(addr))

#define LDMX4T(r0, r1, r2, r3, addr)                                        \
  asm volatile(                                                             \
      "ldmatrix.sync.aligned.m8n8.x4.trans.shared.b16 {%0,%1,%2,%3}, [%4];" \
      : "=r"(r0), "=r"(r1), "=r"(r2), "=r"(r3) : "r"(addr))

__device__ __forceinline__ uint32_t smem_u32(const void* p) {
  uint32_t a;
  asm("{ .reg .u64 t; cvta.to.shared.u64 t, %1; cvt.u32.u64 %0, t; }"
      : "=r"(a) : "l"(p));
  return a;
}
__device__ __forceinline__ void splitH2(float x0, float x1, uint32_t& hi,
                                        uint32_t& lo) {
  __half2 h = __floats2half2_rn(x0, x1);
  float2 hf = __half22float2(h);
  __half2 l = __floats2half2_rn(x0 - hf.x, x1 - hf.y);
  hi = *(uint32_t*)&h;
  lo = *(uint32_t*)&l;
}
__device__ __forceinline__ uint32_t packH2(float x0, float x1) {
  __half2 h = __floats2half2_rn(x0, x1);
  return *(uint32_t*)&h;
}
__device__ __forceinline__ float ex2f(float x) {
  float r;
  asm("ex2.approx.ftz.f32 %0, %1;" : "=f"(r) : "f"(x));
  return r;
}
// swizzled u32 index within an array (row stride 32 u32, 8 chunks of 4 u32)
__device__ __forceinline__ int swz_w(int row, int col) {
  return row * 32 + (col & 3) + ((((col >> 2) ^ row) & 7) << 2);
}

__global__ void __launch_bounds__(256, 2) attn_kernel(
    const float* __restrict__ qg, const float* __restrict__ kg,
    const float* __restrict__ vg, const float* __restrict__ at,
    float* __restrict__ out) {
  extern __shared__ uint32_t sm[];
  float* mk = (float*)(sm + O_MK);
  uint32_t sb = smem_u32(sm);

  int tid = threadIdx.x;
  int w = tid >> 5, lane = tid & 31;
  int quad = lane >> 2, four = lane & 3;
  int bh = blockIdx.y;
  int b = bh >> 4, h = bh & 15;
  int bx = (int)gridDim.x - 1 - (int)blockIdx.x;  // heaviest first
  int row0 = bx * Bb;

  const float sc = 0.125f * 1.44269504f;  // scale * log2(e)
  float alphaeff = at[h] * sc;

  // ---- load Q (scaled) hi-only, swizzled [r 0..127][32 u32] ----
  {
    int r = tid >> 1;
    int cb = 16 * (tid & 1);
    const float* src = qg + ((size_t)((b * LL + row0 + r) * HH + h)) * EE + cb * 2;
#pragma unroll
    for (int u = 0; u < 8; u++) {
      float4 x = *(const float4*)(src + 4 * u);
      uint32_t h01 = packH2(x.x * sc, x.y * sc);
      uint32_t h23 = packH2(x.z * sc, x.w * sc);
      *(uint2*)(sm + O_QHI + swz_w(r, cb + 2 * u)) = make_uint2(h01, h23);
    }
  }

  // fragment address bases (bytes)
  int arow = 16 * w + (lane & 7) + ((lane >> 3) & 1) * 8;
  int ahalf = (lane >> 4) & 1;
  int a7 = arow & 7;
  uint32_t a_base = sb + (uint32_t)(O_QHI + arow * 32) * 4;

  int krow = (lane & 7) + ((lane >> 4) & 1) * 8;
  int khalf = (lane >> 3) & 1;
  int k7 = krow & 7;
  uint32_t k_base = sb + (uint32_t)(O_KHI + krow * 32) * 4;

  int vrow = (lane & 7) + ((lane >> 3) & 1) * 8;
  int vhalf = (lane >> 4) & 1;
  int v7 = vrow & 7;
  uint32_t v_base = sb + (uint32_t)(O_VHI + vrow * 32) * 4;

  const uint32_t HL = 2048u * 4u;  // hi->lo array offset (bytes)

  // momentum for my two rows
  int r0g = row0 + 16 * w + quad;
  int r1g = r0g + 8;
  float mq0 = (r0g > 0) ? (g_fused[b * LL + r0g] - g_fused[b * LL + r0g - 1]) : 0.f;
  float mq1 = (g_fused[b * LL + r1g] - g_fused[b * LL + r1g - 1]);

  float oA[8][4];
#pragma unroll
  for (int nt = 0; nt < 8; nt++)
#pragma unroll
    for (int c = 0; c < 4; c++) oA[nt][c] = 0.f;
  float m0 = -CUDART_INF_F, m1 = -CUDART_INF_F, l0 = 0.f, l1 = 0.f;

  int ntiles = 2 * (bx + 1);
  for (int kt = 0; kt < ntiles; kt++) {
    int c0 = kt * BNk;
    __syncthreads();  // safe to overwrite K/V (covers Q write on kt=0)

    // ---- load K hi/lo, swizzled (64 rows, 4 threads per row) ----
    {
      int r = tid >> 2;
      int cb = 8 * (tid & 3);
      const float* src = kg + ((size_t)((b * LL + c0 + r) * HH + h)) * EE + cb * 2;
#pragma unroll
      for (int u = 0; u < 4; u++) {
        float4 x = *(const float4*)(src + 4 * u);
        uint32_t h01, l01, h23, l23;
        splitH2(x.x, x.y, h01, l01);
        splitH2(x.z, x.w, h23, l23);
        int idx = swz_w(r, cb + 2 * u);
        *(uint2*)(sm + O_KHI + idx) = make_uint2(h01, h23);
        *(uint2*)(sm + O_KLO + idx) = make_uint2(l01, l23);
      }
    }
    // ---- load V hi/lo, swizzled (natural [s][d]; trans in ldmatrix) ----
    {
      int r = tid >> 2;
      int cb = 8 * (tid & 3);
      const float* src = vg + ((size_t)((b * LL + c0 + r) * HH + h)) * DD + cb * 2;
#pragma unroll
      for (int u = 0; u < 4; u++) {
        float4 x = *(const float4*)(src + 4 * u);
        uint32_t h01, l01, h23, l23;
        splitH2(x.x, x.y, h01, l01);
        splitH2(x.z, x.w, h23, l23);
        int idx = swz_w(r, cb + 2 * u);
        *(uint2*)(sm + O_VHI + idx) = make_uint2(h01, h23);
        *(uint2*)(sm + O_VLO + idx) = make_uint2(l01, l23);
      }
    }
    if (tid < BNk) {
      int l = c0 + tid;
      mk[tid] = (l > 0) ? (g_fused[b * LL + l] - g_fused[b * LL + l - 1]) : 0.f;
    }
    __syncthreads();

    // ---- S = Qhi (Khi+Klo)^T : 2 phases, 8 interleaved chains ----
    float sA[8][4];
#pragma unroll
    for (int nt = 0; nt < 8; nt++)
#pragma unroll
      for (int c = 0; c < 4; c++) sA[nt][c] = 0.f;

#pragma unroll
    for (int kk = 0; kk < 4; kk++) {
      uint32_t aq[4];
      LDMX4(aq[0], aq[1], aq[2], aq[3],
            a_base + (uint32_t)((((2 * kk + ahalf) ^ a7) & 7) << 4));
      uint32_t blf[4][4];
      // phase hh: load B-hi per p, MMA immediately (8 chains)
#pragma unroll
      for (int p = 0; p < 4; p++) {
        uint32_t ka = k_base + (uint32_t)(p * 2048) +
                      (uint32_t)((((2 * kk + khalf) ^ k7) & 7) << 4);
        uint32_t b0, b1, b2, b3;
        LDMX4(b0, b1, b2, b3, ka);
        LDMX4(blf[p][0], blf[p][1], blf[p][2], blf[p][3], ka + HL);
        MMA16816(sA[2 * p], aq[0], aq[1], aq[2], aq[3], b0, b1);
        MMA16816(sA[2 * p + 1], aq[0], aq[1], aq[2], aq[3], b2, b3);
      }
      // phase hl
#pragma unroll
      for (int p = 0; p < 4; p++) {
        MMA16816(sA[2 * p], aq[0], aq[1], aq[2], aq[3], blf[p][0], blf[p][1]);
        MMA16816(sA[2 * p + 1], aq[0], aq[1], aq[2], aq[3], blf[p][2], blf[p][3]);
      }
    }

    // ---- bias + causal mask + online softmax (base-2) ----
    float mx0 = -CUDART_INF_F, mx1 = -CUDART_INF_F;
    bool diag = (kt >= 2 * bx);
#pragma unroll
    for (int nt = 0; nt < 8; nt++) {
      int cA = nt * 8 + four * 2;
      float mkA = mk[cA], mkB = mk[cA + 1];
      float x0 = sA[nt][0] - alphaeff * fabsf(mq0 - mkA);
      float x1 = sA[nt][1] - alphaeff * fabsf(mq0 - mkB);
      float x2 = sA[nt][2] - alphaeff * fabsf(mq1 - mkA);
      float x3 = sA[nt][3] - alphaeff * fabsf(mq1 - mkB);
      if (diag) {
        int cg = c0 + cA;
        x0 = (cg <= r0g) ? x0 : -CUDART_INF_F;
        x1 = (cg + 1 <= r0g) ? x1 : -CUDART_INF_F;
        x2 = (cg <= r1g) ? x2 : -CUDART_INF_F;
        x3 = (cg + 1 <= r1g) ? x3 : -CUDART_INF_F;
      }
      sA[nt][0] = x0; sA[nt][1] = x1; sA[nt][2] = x2; sA[nt][3] = x3;
      mx0 = fmaxf(mx0, fmaxf(x0, x1));
      mx1 = fmaxf(mx1, fmaxf(x2, x3));
    }
    mx0 = fmaxf(mx0, __shfl_xor_sync(0xffffffffu, mx0, 1));
    mx0 = fmaxf(mx0, __shfl_xor_sync(0xffffffffu, mx0, 2));
    mx1 = fmaxf(mx1, __shfl_xor_sync(0xffffffffu, mx1, 1));
    mx1 = fmaxf(mx1, __shfl_xor_sync(0xffffffffu, mx1, 2));

    float mn0 = fmaxf(m0, mx0), mn1 = fmaxf(m1, mx1);
    float al0 = ex2f(m0 - mn0), al1 = ex2f(m1 - mn1);
    m0 = mn0; m1 = mn1;

    float rs0 = 0.f, rs1 = 0.f;
#pragma unroll
    for (int nt = 0; nt < 8; nt++) {
      float e0v = ex2f(sA[nt][0] - mn0);
      float e1v = ex2f(sA[nt][1] - mn0);
      float e2v = ex2f(sA[nt][2] - mn1);
      float e3v = ex2f(sA[nt][3] - mn1);
      sA[nt][0] = e0v; sA[nt][1] = e1v; sA[nt][2] = e2v; sA[nt][3] = e3v;
      rs0 += e0v + e1v;
      rs1 += e2v + e3v;
    }
    rs0 += __shfl_xor_sync(0xffffffffu, rs0, 1);
    rs0 += __shfl_xor_sync(0xffffffffu, rs0, 2);
    rs1 += __shfl_xor_sync(0xffffffffu, rs1, 1);
    rs1 += __shfl_xor_sync(0xffffffffu, rs1, 2);
    l0 = l0 * al0 + rs0;
    l1 = l1 * al1 + rs1;

    // rescale O
#pragma unroll
    for (int nt = 0; nt < 8; nt++) {
      oA[nt][0] *= al0; oA[nt][1] *= al0;
      oA[nt][2] *= al1; oA[nt][3] *= al1;
    }

    // ---- pack P fragments (hi only) ----
    uint32_t ph[4][4];
#pragma unroll
    for (int t = 0; t < 4; t++) {
      ph[t][0] = packH2(sA[2 * t][0], sA[2 * t][1]);
      ph[t][1] = packH2(sA[2 * t][2], sA[2 * t][3]);
      ph[t][2] = packH2(sA[2 * t + 1][0], sA[2 * t + 1][1]);
      ph[t][3] = packH2(sA[2 * t + 1][2], sA[2 * t + 1][3]);
    }

    // ---- O += Phi (Vhi+Vlo) : per t, 2 phases, 8 interleaved chains ----
#pragma unroll
    for (int t = 0; t < 4; t++) {
      uint32_t vlf[4][4];
#pragma unroll
      for (int p = 0; p < 4; p++) {
        uint32_t va = v_base + (uint32_t)(t * 2048) +
                      (uint32_t)((((2 * p + vhalf) ^ v7) & 7) << 4);
        uint32_t b0, b1, b2, b3;
        LDMX4T(b0, b1, b2, b3, va);
        LDMX4T(vlf[p][0], vlf[p][1], vlf[p][2], vlf[p][3], va + HL);
        MMA16816(oA[2 * p], ph[t][0], ph[t][1], ph[t][2], ph[t][3], b0, b1);
        MMA16816(oA[2 * p + 1], ph[t][0], ph[t][1], ph[t][2], ph[t][3], b2, b3);
      }
#pragma unroll
      for (int p = 0; p < 4; p++) {
        MMA16816(oA[2 * p], ph[t][0], ph[t][1], ph[t][2], ph[t][3], vlf[p][0], vlf[p][1]);
        MMA16816(oA[2 * p + 1], ph[t][0], ph[t][1], ph[t][2], ph[t][3], vlf[p][2], vlf[p][3]);
      }
    }
  }

  // ---- epilogue ----
  float inv0 = 1.f / l0, inv1 = 1.f / l1;
  float* d0p = out + ((size_t)((b * LL + r0g) * HH + h)) * DD;
  float* d1p = out + ((size_t)((b * LL + r1g) * HH + h)) * DD;
#pragma unroll
  for (int nt = 0; nt < 8; nt++) {
    int c = nt * 8 + four * 2;
    *(float2*)(d0p + c) = make_float2(oA[nt][0] * inv0, oA[nt][1] * inv0);
    *(float2*)(d1p + c) = make_float2(oA[nt][2] * inv1, oA[nt][3] * inv1);
  }
}

// ---------------------------------------------------------------------------
extern "C" void kernel_launch(void* const* d_in, const int* in_sizes, int n_in,
                              void* d_out, int out_size) {
  const float* q = (const float*)d_in[0];
  const float* k = (const float*)d_in[1];
  const float* v = (const float*)d_in[2];
  const float* raw = (const float*)d_in[3];
  const float* w1 = (const float*)d_in[4];
  const float* b1 = (const float*)d_in[5];
  const float* w2 = (const float*)d_in[6];
  const float* b2 = (const float*)d_in[7];
  const float* at = (const float*)d_in[8];
  float* out = (float*)d_out;

  mlp_kernel<<<(BB * LL) / POS, 256>>>(raw, w1, b1, w2, b2);

  cudaFuncSetAttribute(attn_kernel, cudaFuncAttributeMaxDynamicSharedMemorySize,
                       ATT_SMEM);
  dim3 grid(LL / Bb, BB * HH);
  attn_kernel<<<grid, 256, ATT_SMEM>>>(q, k, v, at, out);
}